// round 10
// baseline (speedup 1.0000x reference)
#include <cuda_runtime.h>
#include <cuda_fp16.h>
#include <cstdint>
#include <cstddef>

#define NTOK 4096
#define DQK  64
#define CVCH 256
#define NB   4
#define TQ   64
#define TK   64
#define NT   (NTOK / TK)   // 64

__device__ __align__(16) __half g_q16[NB * NTOK * 128];     // [b][n][hi64|lo64]
__device__ __align__(16) __half g_k16[NB * NTOK * 128];
__device__ __align__(16) __half g_v16[NB * NT * CVCH * TK]; // [b][t][c][64j]

__device__ __forceinline__ float fast_exp2(float x) {
    float r; asm("ex2.approx.ftz.f32 %0, %1;" : "=f"(r) : "f"(x)); return r;
}
__device__ __forceinline__ uint32_t smem_u32(const void* p) {
    uint32_t a;
    asm("{ .reg .u64 t; cvta.to.shared.u64 t, %1; cvt.u32.u64 %0, t; }" : "=r"(a) : "l"(p));
    return a;
}
#define MMA16(d, a0, a1, a2, a3, b0, b1) \
    asm volatile("mma.sync.aligned.m16n8k16.row.col.f32.f16.f16.f32 " \
        "{%0,%1,%2,%3}, {%4,%5,%6,%7}, {%8,%9}, {%0,%1,%2,%3};" \
        : "+f"((d)[0]), "+f"((d)[1]), "+f"((d)[2]), "+f"((d)[3]) \
        : "r"(a0), "r"(a1), "r"(a2), "r"(a3), "r"(b0), "r"(b1))
#define LDSM4(r0, r1, r2, r3, a) \
    asm volatile("ldmatrix.sync.aligned.m8n8.x4.shared.b16 {%0,%1,%2,%3},[%4];" \
        : "=r"(r0), "=r"(r1), "=r"(r2), "=r"(r3) : "r"(a))
#define LDSM4T(r0, r1, r2, r3, a) \
    asm volatile("ldmatrix.sync.aligned.m8n8.x4.trans.shared.b16 {%0,%1,%2,%3},[%4];" \
        : "=r"(r0), "=r"(r1), "=r"(r2), "=r"(r3) : "r"(a))
#define CP16(dst, src) \
    asm volatile("cp.async.cg.shared.global [%0], [%1], 16;" :: "r"(dst), "l"(src))
#define CPCOMMIT() asm volatile("cp.async.commit_group;")
#define CPWAITG(N) asm volatile("cp.async.wait_group %0;" :: "n"(N) : "memory")

__device__ __forceinline__ void split8(const float4 x, uint2& hi, uint2& lo) {
    __half h0 = __float2half_rn(x.x), h1 = __float2half_rn(x.y);
    __half h2 = __float2half_rn(x.z), h3 = __float2half_rn(x.w);
    __half e0 = __float2half_rn(x.x - __half2float(h0));
    __half e1 = __float2half_rn(x.y - __half2float(h1));
    __half e2 = __float2half_rn(x.z - __half2float(h2));
    __half e3 = __float2half_rn(x.w - __half2float(h3));
    __half2 a = __halves2half2(h0, h1), b = __halves2half2(h2, h3);
    __half2 c = __halves2half2(e0, e1), d = __halves2half2(e2, e3);
    hi.x = *(uint32_t*)&a; hi.y = *(uint32_t*)&b;
    lo.x = *(uint32_t*)&c; lo.y = *(uint32_t*)&d;
}

// attn smem: half-index offsets (rows stride 72) unless byte-marked.
#define SQH 0        // [64][72] q hi
#define SQL 4608     // q lo
#define SKH 9216     // [64][72] k hi (single buffer)
#define SKL 13824    // k lo
#define SP  18432    // [64][72] p
#define VBB 46080    // BYTE: 2 bufs x V[256 rows][128B], XOR-swizzled
#define FOFFB 111616 // BYTE: float region
#define RM 0         // [64][2]
#define LR 128       // [64][2]
#define ATTN_SMEM (FOFFB + 256 * 4)   // 112,640 B -> 2 CTAs/SM

// ---------------------------------------------------------------------------
// conv q/k: fp16 3-pass GEMM (validated R8/R9)
// ---------------------------------------------------------------------------
__global__ __launch_bounds__(256)
void conv_qk_mma(const float* __restrict__ X, const float* __restrict__ W,
                 const float* __restrict__ bias, __half* __restrict__ Y,
                 int C, float scale) {
    __shared__ __half smc[13824];
    __shared__ float sbias[64];
    const int XL = 4352, WH = 8704, WL = 11264;
    const int b = blockIdx.z, n0 = blockIdx.x << 7;
    const int tid = threadIdx.x, lane = tid & 31, w = tid >> 5;
    const int gid = lane >> 2, tig = lane & 3, lr = lane & 15, lc = (lane >> 4) << 3;
    const uint32_t sb = smem_u32(smc);
    if (tid < 64) sbias[tid] = bias[tid];
    float acc[8][4];
    #pragma unroll
    for (int i = 0; i < 8; i++)
        #pragma unroll
        for (int e = 0; e < 4; e++) acc[i][e] = 0.f;

    for (int c0 = 0; c0 < C; c0 += 32) {
        __syncthreads();
        #pragma unroll
        for (int p = 0; p < 4; p++) {
            int idx = tid + p * 256, cc = idx >> 5, n4 = (idx & 31) << 2;
            float4 x = *reinterpret_cast<const float4*>(X + ((size_t)b * C + c0 + cc) * NTOK + n0 + n4);
            uint2 hi, lo; split8(x, hi, lo);
            *reinterpret_cast<uint2*>(smc + cc * 136 + n4) = hi;
            *reinterpret_cast<uint2*>(smc + XL + cc * 136 + n4) = lo;
        }
        #pragma unroll
        for (int p = 0; p < 2; p++) {
            int idx = tid + p * 256, oo = idx >> 3, c4 = (idx & 7) << 2;
            float4 x = *reinterpret_cast<const float4*>(W + (size_t)oo * C + c0 + c4);
            uint2 hi, lo; split8(x, hi, lo);
            *reinterpret_cast<uint2*>(smc + WH + oo * 40 + c4) = hi;
            *reinterpret_cast<uint2*>(smc + WL + oo * 40 + c4) = lo;
        }
        __syncthreads();
        #pragma unroll
        for (int ks = 0; ks < 2; ks++) {
            uint32_t ah0, ah1, ah2, ah3, al0, al1, al2, al3;
            uint32_t ax = sb + 2u * (((ks << 4) + (lane & 7) + ((lane >> 4) << 3)) * 136
                                     + (w << 4) + (((lane >> 3) & 1) << 3));
            LDSM4T(ah0, ah1, ah2, ah3, ax);
            LDSM4T(al0, al1, al2, al3, ax + 2u * XL);
            #pragma unroll
            for (int p = 0; p < 4; p++) {
                uint32_t bh0, bh1, bh2, bh3, bl0, bl1, bl2, bl3;
                uint32_t aw = sb + 2u * (WH + ((p << 4) + lr) * 40 + (ks << 4) + lc);
                LDSM4(bh0, bh1, bh2, bh3, aw);
                LDSM4(bl0, bl1, bl2, bl3, aw + 2u * (WL - WH));
                MMA16(acc[2 * p],     ah0, ah1, ah2, ah3, bh0, bh2);
                MMA16(acc[2 * p + 1], ah0, ah1, ah2, ah3, bh1, bh3);
                MMA16(acc[2 * p],     ah0, ah1, ah2, ah3, bl0, bl2);
                MMA16(acc[2 * p + 1], ah0, ah1, ah2, ah3, bl1, bl3);
                MMA16(acc[2 * p],     al0, al1, al2, al3, bh0, bh2);
                MMA16(acc[2 * p + 1], al0, al1, al2, al3, bh1, bh3);
            }
        }
    }
    const int tok0 = n0 + (w << 4) + gid;
    #pragma unroll
    for (int nt = 0; nt < 8; nt++) {
        const int c = nt * 8 + 2 * tig;
        float b0s = sbias[c], b1s = sbias[c + 1];
        #pragma unroll
        for (int rr = 0; rr < 2; rr++) {
            float v0 = (acc[nt][2 * rr] + b0s) * scale;
            float v1 = (acc[nt][2 * rr + 1] + b1s) * scale;
            __half h0 = __float2half_rn(v0), h1 = __float2half_rn(v1);
            __half2 hh = __halves2half2(h0, h1);
            __half2 ll = __halves2half2(__float2half_rn(v0 - __half2float(h0)),
                                        __float2half_rn(v1 - __half2float(h1)));
            __half* yp = Y + ((size_t)b * NTOK + tok0 + rr * 8) * 128 + c;
            *(uint32_t*)yp = *(uint32_t*)&hh;
            *(uint32_t*)(yp + 64) = *(uint32_t*)&ll;
        }
    }
}

// conv v: single-pass fp16 GEMM, tiled output (validated R8/R9)
__global__ __launch_bounds__(256)
void conv_v_mma(const float* __restrict__ X, const float* __restrict__ W,
                const float* __restrict__ bias, __half* __restrict__ Y, int C) {
    __shared__ __half smc[9472];
    __shared__ float sbias[128];
    const int WHo = 4352;
    const int b = blockIdx.z, o0 = blockIdx.y << 7, n0 = blockIdx.x << 7;
    const int tid = threadIdx.x, lane = tid & 31, w = tid >> 5;
    const int gid = lane >> 2, tig = lane & 3, lr = lane & 15, lc = (lane >> 4) << 3;
    const uint32_t sb = smem_u32(smc);
    if (tid < 128) sbias[tid] = bias[o0 + tid];
    float acc[16][4];
    #pragma unroll
    for (int i = 0; i < 16; i++)
        #pragma unroll
        for (int e = 0; e < 4; e++) acc[i][e] = 0.f;

    for (int c0 = 0; c0 < C; c0 += 32) {
        __syncthreads();
        #pragma unroll
        for (int p = 0; p < 4; p++) {
            int idx = tid + p * 256, cc = idx >> 5, n4 = (idx & 31) << 2;
            float4 x = *reinterpret_cast<const float4*>(X + ((size_t)b * C + c0 + cc) * NTOK + n0 + n4);
            __half2 p0 = __floats2half2_rn(x.x, x.y), p1 = __floats2half2_rn(x.z, x.w);
            uint2 u; u.x = *(uint32_t*)&p0; u.y = *(uint32_t*)&p1;
            *reinterpret_cast<uint2*>(smc + cc * 136 + n4) = u;
        }
        #pragma unroll
        for (int p = 0; p < 4; p++) {
            int idx = tid + p * 256, oo = idx >> 3, c4 = (idx & 7) << 2;
            float4 x = *reinterpret_cast<const float4*>(W + (size_t)(o0 + oo) * C + c0 + c4);
            __half2 p0 = __floats2half2_rn(x.x, x.y), p1 = __floats2half2_rn(x.z, x.w);
            uint2 u; u.x = *(uint32_t*)&p0; u.y = *(uint32_t*)&p1;
            *reinterpret_cast<uint2*>(smc + WHo + oo * 40 + c4) = u;
        }
        __syncthreads();
        #pragma unroll
        for (int ks = 0; ks < 2; ks++) {
            uint32_t a0, a1, a2, a3;
            LDSM4(a0, a1, a2, a3, sb + 2u * (WHo + ((w << 4) + lr) * 40 + (ks << 4) + lc));
            #pragma unroll
            for (int tp = 0; tp < 8; tp++) {
                uint32_t v0, v1, v2, v3;
                uint32_t ax = sb + 2u * (((ks << 4) + (lane & 7) + ((lane >> 4) << 3)) * 136
                                         + (tp << 4) + (((lane >> 3) & 1) << 3));
                LDSM4T(v0, v1, v2, v3, ax);
                MMA16(acc[2 * tp],     a0, a1, a2, a3, v0, v2);
                MMA16(acc[2 * tp + 1], a0, a1, a2, a3, v1, v3);
            }
        }
    }
    const int orow = (w << 4) + gid;
    float br0 = sbias[orow], br1 = sbias[orow + 8];
    __half* vbo = Y + ((size_t)b * NT + (n0 >> 6)) * CVCH * 64;
    #pragma unroll
    for (int nt = 0; nt < 16; nt++) {
        int tokoff = nt * 8 + 2 * tig;
        int tadd = tokoff >> 6, j = tokoff & 63;
        __half2 h0 = __floats2half2_rn(acc[nt][0] + br0, acc[nt][1] + br0);
        __half2 h1 = __floats2half2_rn(acc[nt][2] + br1, acc[nt][3] + br1);
        __half* p0 = vbo + ((size_t)tadd * CVCH + o0 + orow) * 64 + j;
        *(uint32_t*)p0 = *(uint32_t*)&h0;
        *(uint32_t*)(p0 + 8 * 64) = *(uint32_t*)&h1;
    }
}

// ---------------------------------------------------------------------------
// Flash attention, software-pipelined: region = PV(t-1) + S(t) fused (no
// barrier between tensor phases), 2 syncs/tile, conditional O-rescale skip.
// K single-buffered, V double-buffered. TQ=64, 256 thr, 2 CTAs/SM.
// ---------------------------------------------------------------------------
__global__ __launch_bounds__(256, 2)
void attn_kernel(const float* __restrict__ skip, const float* __restrict__ gamma,
                 float* __restrict__ out) {
    extern __shared__ __align__(16) char sm[];
    __half* smh = (__half*)sm;
    float* smf = (float*)(sm + FOFFB);
    const uint32_t sb = smem_u32(sm);
    const int tid = threadIdx.x, lane = tid & 31, w = tid >> 5;
    const int gid = lane >> 2, tig = lane & 3, lr = lane & 15, lc = (lane >> 4) << 3;
    const int r0 = (w & 3) << 4;            // S rows
    const int ch = w >> 2;                  // S col half (32 cols)
    const int rq = (w & 1) << 5, cq = (w >> 1) << 6;   // PV partition
    const int b = blockIdx.y, i0 = blockIdx.x * TQ;
    const int row0 = r0 + gid, row1 = row0 + 8;

    const __half* qb = g_q16 + (size_t)b * NTOK * 128;
    const __half* kb = g_k16 + (size_t)b * NTOK * 128;
    const __half* vbg = g_v16 + (size_t)b * NT * CVCH * TK;

    // prologue: {Q,K0} group, {V0} group
    #pragma unroll
    for (int p = 0; p < 4; p++) {
        int chunk = tid + p * 256, row = chunk >> 4, c16 = chunk & 15;
        uint32_t d = sb + 2u * (c16 < 8 ? SQH + row * 72 + c16 * 8
                                        : SQL + row * 72 + (c16 - 8) * 8);
        CP16(d, qb + (size_t)(i0 + row) * 128 + c16 * 8);
    }
    #pragma unroll
    for (int p = 0; p < 4; p++) {
        int chunk = tid + p * 256, row = chunk >> 4, c16 = chunk & 15;
        uint32_t d = sb + 2u * (c16 < 8 ? SKH + row * 72 + c16 * 8
                                        : SKL + row * 72 + (c16 - 8) * 8);
        CP16(d, kb + (size_t)row * 128 + c16 * 8);
    }
    CPCOMMIT();
    #pragma unroll
    for (int p = 0; p < 8; p++) {
        int chunk = tid + p * 256, row = chunk >> 3, cb = chunk & 7;
        uint32_t d = sb + VBB + row * 128 + (((uint32_t)(cb ^ (row & 7))) << 4);
        CP16(d, vbg + (size_t)row * 64 + cb * 8);
    }
    CPCOMMIT();

    float oacc[16][4];
    #pragma unroll
    for (int t = 0; t < 16; t++)
        #pragma unroll
        for (int e = 0; e < 4; e++) oacc[t][e] = 0.f;
    float rm0 = -1e30f, rm1 = -1e30f, lsum0 = 0.f, lsum1 = 0.f;
    float rmp[4];
    #pragma unroll
    for (int e = 0; e < 4; e++) rmp[e] = -1e30f;

    CPWAITG(1);        // Q, K0 ready (V0 may pend)
    __syncthreads();

    for (int t = 0; t < NT; t++) {
        // ==== REGION: S(t) fused with PV(t-1) ====
        const int vbuf = (t - 1) & 1;       // V(t-1) buffer (unused when t==0)
        float sacc[4][4];
        #pragma unroll
        for (int tt = 0; tt < 4; tt++)
            #pragma unroll
            for (int e = 0; e < 4; e++) sacc[tt][e] = 0.f;
        #pragma unroll
        for (int kk = 0; kk < 4; kk++) {
            // S sub-step
            uint32_t ah0, ah1, ah2, ah3, al0, al1, al2, al3;
            uint32_t aq = sb + 2u * (SQH + (r0 + lr) * 72 + kk * 16 + lc);
            LDSM4(ah0, ah1, ah2, ah3, aq);
            LDSM4(al0, al1, al2, al3, aq + 2u * SQL);
            #pragma unroll
            for (int tp = 0; tp < 2; tp++) {
                uint32_t bh0, bh1, bh2, bh3, bl0, bl1, bl2, bl3;
                uint32_t ak = sb + 2u * (SKH + (ch * 32 + tp * 16 + lr) * 72 + kk * 16 + lc);
                LDSM4(bh0, bh1, bh2, bh3, ak);
                LDSM4(bl0, bl1, bl2, bl3, ak + 2u * 4608);
                MMA16(sacc[2 * tp],     ah0, ah1, ah2, ah3, bh0, bh2);
                MMA16(sacc[2 * tp + 1], ah0, ah1, ah2, ah3, bh1, bh3);
                MMA16(sacc[2 * tp],     ah0, ah1, ah2, ah3, bl0, bl2);
                MMA16(sacc[2 * tp + 1], ah0, ah1, ah2, ah3, bl1, bl3);
                MMA16(sacc[2 * tp],     al0, al1, al2, al3, bh0, bh2);
                MMA16(sacc[2 * tp + 1], al0, al1, al2, al3, bh1, bh3);
            }
            // PV sub-step (previous tile), interleaved
            if (t > 0) {
                uint32_t pa0, pa1, pa2, pa3, qa0, qa1, qa2, qa3;
                uint32_t ap = sb + 2u * (SP + (rq + lr) * 72 + kk * 16 + lc);
                LDSM4(pa0, pa1, pa2, pa3, ap);
                LDSM4(qa0, qa1, qa2, qa3, ap + 2u * (16 * 72));
                const uint32_t cb = (uint32_t)(kk * 2 + (lc >> 3));
                #pragma unroll
                for (int np = 0; np < 4; np++) {
                    const int vrow = cq + np * 16 + lr;
                    uint32_t va = sb + VBB + (uint32_t)vbuf * 32768u + vrow * 128
                                + ((cb ^ (uint32_t)(vrow & 7)) << 4);
                    uint32_t v0, v1, v2, v3;
                    LDSM4(v0, v1, v2, v3, va);
                    MMA16(oacc[2 * np],         pa0, pa1, pa2, pa3, v0, v2);
                    MMA16(oacc[2 * np + 1],     pa0, pa1, pa2, pa3, v1, v3);
                    MMA16(oacc[8 + 2 * np],     qa0, qa1, qa2, qa3, v0, v2);
                    MMA16(oacc[8 + 2 * np + 1], qa0, qa1, qa2, qa3, v1, v3);
                }
            }
        }
        // warp partial row-max -> RM
        float mx0 = -1e30f, mx1 = -1e30f;
        #pragma unroll
        for (int tt = 0; tt < 4; tt++) {
            mx0 = fmaxf(mx0, fmaxf(sacc[tt][0], sacc[tt][1]));
            mx1 = fmaxf(mx1, fmaxf(sacc[tt][2], sacc[tt][3]));
        }
        mx0 = fmaxf(mx0, __shfl_xor_sync(0xFFFFFFFFu, mx0, 1));
        mx0 = fmaxf(mx0, __shfl_xor_sync(0xFFFFFFFFu, mx0, 2));
        mx1 = fmaxf(mx1, __shfl_xor_sync(0xFFFFFFFFu, mx1, 1));
        mx1 = fmaxf(mx1, __shfl_xor_sync(0xFFFFFFFFu, mx1, 2));
        if (tig == 0) {
            smf[RM + row0 * 2 + ch] = mx0;
            smf[RM + row1 * 2 + ch] = mx1;
        }
        __syncthreads();   // RM visible; K buffer + V(t-1) + P(t-1) consumed

        // issue K(t+1) then V(t+1) (separate groups)
        if (t + 1 < NT) {
            #pragma unroll
            for (int p = 0; p < 4; p++) {
                int chunk = tid + p * 256, row = chunk >> 4, c16 = chunk & 15;
                uint32_t d = sb + 2u * (c16 < 8 ? SKH + row * 72 + c16 * 8
                                                : SKL + row * 72 + (c16 - 8) * 8);
                CP16(d, kb + (size_t)((t + 1) * TK + row) * 128 + c16 * 8);
            }
            CPCOMMIT();
            const __half* vt = vbg + (size_t)(t + 1) * CVCH * TK;
            #pragma unroll
            for (int p = 0; p < 8; p++) {
                int chunk = tid + p * 256, row = chunk >> 3, cb = chunk & 7;
                uint32_t d = sb + VBB + (uint32_t)((t + 1) & 1) * 32768u + row * 128
                           + (((uint32_t)(cb ^ (row & 7))) << 4);
                CP16(d, vt + (size_t)row * 64 + cb * 8);
            }
            CPCOMMIT();
        }

        // ==== SOFTMAX(t) ====
        float mn0 = fmaxf(rm0, fmaxf(smf[RM + row0 * 2], smf[RM + row0 * 2 + 1]));
        float mn1 = fmaxf(rm1, fmaxf(smf[RM + row1 * 2], smf[RM + row1 * 2 + 1]));
        float f0 = fast_exp2(rm0 - mn0), f1 = fast_exp2(rm1 - mn1);
        rm0 = mn0; rm1 = mn1;
        // PV-row rescale factors (same max sequence -> bit-identical scales)
        float fr[4];
        #pragma unroll
        for (int e = 0; e < 4; e++) {
            const int rr = rq + gid + 8 * e;
            float m = fmaxf(rmp[e], fmaxf(smf[RM + rr * 2], smf[RM + rr * 2 + 1]));
            fr[e] = fast_exp2(rmp[e] - m);
            rmp[e] = m;
        }
        if (!__all_sync(0xFFFFFFFFu,
                        (fr[0] == 1.f) & (fr[1] == 1.f) & (fr[2] == 1.f) & (fr[3] == 1.f))) {
            #pragma unroll
            for (int nt = 0; nt < 8; nt++) {
                oacc[nt][0] *= fr[0]; oacc[nt][1] *= fr[0];
                oacc[nt][2] *= fr[1]; oacc[nt][3] *= fr[1];
                oacc[8 + nt][0] *= fr[2]; oacc[8 + nt][1] *= fr[2];
                oacc[8 + nt][2] *= fr[3]; oacc[8 + nt][3] *= fr[3];
            }
        }
        float ps0 = 0.f, ps1 = 0.f;
        #pragma unroll
        for (int tt = 0; tt < 4; tt++) {
            float p00 = fast_exp2(sacc[tt][0] - mn0);
            float p01 = fast_exp2(sacc[tt][1] - mn0);
            float p10 = fast_exp2(sacc[tt][2] - mn1);
            float p11 = fast_exp2(sacc[tt][3] - mn1);
            ps0 += p00 + p01; ps1 += p10 + p11;
            __half2 h0 = __floats2half2_rn(p00, p01);
            __half2 h1 = __floats2half2_rn(p10, p11);
            const int cc = ch * 32 + tt * 8 + 2 * tig;
            *(uint32_t*)(smh + SP + row0 * 72 + cc) = *(uint32_t*)&h0;
            *(uint32_t*)(smh + SP + row1 * 72 + cc) = *(uint32_t*)&h1;
        }
        lsum0 = lsum0 * f0 + ps0;
        lsum1 = lsum1 * f1 + ps1;
        if (t + 1 < NT) { CPWAITG(1); } else { CPWAITG(0); }
        __syncthreads();   // P(t) visible; K(t+1), V(t) ready
    }

    // ==== final PV(NT-1) ====
    {
        const int vbuf = (NT - 1) & 1;
        #pragma unroll
        for (int kk = 0; kk < 4; kk++) {
            uint32_t pa0, pa1, pa2, pa3, qa0, qa1, qa2, qa3;
            uint32_t ap = sb + 2u * (SP + (rq + lr) * 72 + kk * 16 + lc);
            LDSM4(pa0, pa1, pa2, pa3, ap);
            LDSM4(qa0, qa1, qa2, qa3, ap + 2u * (16 * 72));
            const uint32_t cb = (uint32_t)(kk * 2 + (lc >> 3));
            #pragma unroll
            for (int np = 0; np < 4; np++) {
                const int vrow = cq + np * 16 + lr;
                uint32_t va = sb + VBB + (uint32_t)vbuf * 32768u + vrow * 128
                            + ((cb ^ (uint32_t)(vrow & 7)) << 4);
                uint32_t v0, v1, v2, v3;
                LDSM4(v0, v1, v2, v3, va);
                MMA16(oacc[2 * np],         pa0, pa1, pa2, pa3, v0, v2);
                MMA16(oacc[2 * np + 1],     pa0, pa1, pa2, pa3, v1, v3);
                MMA16(oacc[8 + 2 * np],     qa0, qa1, qa2, qa3, v0, v2);
                MMA16(oacc[8 + 2 * np + 1], qa0, qa1, qa2, qa3, v1, v3);
            }
        }
    }

    // final l reduction + epilogue
    lsum0 += __shfl_xor_sync(0xFFFFFFFFu, lsum0, 1);
    lsum0 += __shfl_xor_sync(0xFFFFFFFFu, lsum0, 2);
    lsum1 += __shfl_xor_sync(0xFFFFFFFFu, lsum1, 1);
    lsum1 += __shfl_xor_sync(0xFFFFFFFFu, lsum1, 2);
    __syncthreads();
    if (tig == 0) {
        smf[LR + row0 * 2 + ch] = lsum0;
        smf[LR + row1 * 2 + ch] = lsum1;
    }
    __syncthreads();

    const float gm = __ldg(gamma);
    const float* skb = skip + (size_t)b * CVCH * NTOK;
    float* ob = out + (size_t)b * CVCH * NTOK;
    #pragma unroll
    for (int mt = 0; mt < 2; mt++) {
        const int ra = rq + mt * 16 + gid, rb = ra + 8;
        const float fca = gm / (smf[LR + ra * 2] + smf[LR + ra * 2 + 1]);
        const float fcb = gm / (smf[LR + rb * 2] + smf[LR + rb * 2 + 1]);
        const int ia = i0 + ra, ib = i0 + rb;
        #pragma unroll
        for (int nt = 0; nt < 8; nt++) {
            const int c = cq + nt * 8 + 2 * tig;
            const size_t oA = (size_t)c * NTOK, oB = (size_t)(c + 1) * NTOK;
            const float* acc = oacc[mt * 8 + nt];
            ob[oA + ia] = acc[0] * fca + skb[oA + ia];
            ob[oB + ia] = acc[1] * fca + skb[oB + ia];
            ob[oA + ib] = acc[2] * fcb + skb[oA + ib];
            ob[oB + ib] = acc[3] * fcb + skb[oB + ib];
        }
    }
}

// ---------------------------------------------------------------------------
static __half* s_q = nullptr;
static __half* s_k = nullptr;
static __half* s_v = nullptr;

extern "C" void kernel_launch(void* const* d_in, const int* in_sizes, int n_in,
                              void* d_out, int out_size) {
    (void)in_sizes; (void)n_in; (void)out_size;
    static bool initialized = []() {
        void* p;
        cudaGetSymbolAddress(&p, g_q16); s_q = (__half*)p;
        cudaGetSymbolAddress(&p, g_k16); s_k = (__half*)p;
        cudaGetSymbolAddress(&p, g_v16); s_v = (__half*)p;
        cudaFuncSetAttribute(attn_kernel, cudaFuncAttributeMaxDynamicSharedMemorySize,
                             ATTN_SMEM);
        return true;
    }();
    (void)initialized;

    const float* gate  = (const float*)d_in[0];
    const float* skip  = (const float*)d_in[1];
    const float* Wq    = (const float*)d_in[2];
    const float* bq    = (const float*)d_in[3];
    const float* Wk    = (const float*)d_in[4];
    const float* bk    = (const float*)d_in[5];
    const float* Wv    = (const float*)d_in[6];
    const float* bv    = (const float*)d_in[7];
    const float* gamma = (const float*)d_in[8];
    float* out = (float*)d_out;

    const float LOG2E = 1.4426950408889634f;

    conv_qk_mma<<<dim3(32, 1, NB), 256>>>(gate, Wq, bq, s_q, 512, LOG2E);
    conv_qk_mma<<<dim3(32, 1, NB), 256>>>(skip, Wk, bk, s_k, 256, 1.0f);
    conv_v_mma <<<dim3(32, 2, NB), 256>>>(skip, Wv, bv, s_v, 256);
    attn_kernel<<<dim3(NTOK / TQ, NB), 256, ATTN_SMEM>>>(skip, gamma, out);
}

// round 11
// speedup vs baseline: 1.0486x; 1.0486x over previous
#include <cuda_runtime.h>
#include <cuda_fp16.h>
#include <cstdint>
#include <cstddef>

#define NTOK 4096
#define DQK  64
#define CVCH 256
#define NB   4
#define TQ   64
#define TK   64
#define NT   (NTOK / TK)   // 64

__device__ __align__(16) __half g_q16[NB * NTOK * 128];     // [b][n][hi64|lo64]
__device__ __align__(16) __half g_k16[NB * NTOK * 128];
__device__ __align__(16) __half g_v16[NB * NT * CVCH * TK]; // [b][t][c][64j]

__device__ __forceinline__ float fast_exp2(float x) {
    float r; asm("ex2.approx.ftz.f32 %0, %1;" : "=f"(r) : "f"(x)); return r;
}
__device__ __forceinline__ uint32_t smem_u32(const void* p) {
    uint32_t a;
    asm("{ .reg .u64 t; cvta.to.shared.u64 t, %1; cvt.u32.u64 %0, t; }" : "=r"(a) : "l"(p));
    return a;
}
#define MMA16(d, a0, a1, a2, a3, b0, b1) \
    asm volatile("mma.sync.aligned.m16n8k16.row.col.f32.f16.f16.f32 " \
        "{%0,%1,%2,%3}, {%4,%5,%6,%7}, {%8,%9}, {%0,%1,%2,%3};" \
        : "+f"((d)[0]), "+f"((d)[1]), "+f"((d)[2]), "+f"((d)[3]) \
        : "r"(a0), "r"(a1), "r"(a2), "r"(a3), "r"(b0), "r"(b1))
#define LDSM4(r0, r1, r2, r3, a) \
    asm volatile("ldmatrix.sync.aligned.m8n8.x4.shared.b16 {%0,%1,%2,%3},[%4];" \
        : "=r"(r0), "=r"(r1), "=r"(r2), "=r"(r3) : "r"(a))
#define LDSM4T(r0, r1, r2, r3, a) \
    asm volatile("ldmatrix.sync.aligned.m8n8.x4.trans.shared.b16 {%0,%1,%2,%3},[%4];" \
        : "=r"(r0), "=r"(r1), "=r"(r2), "=r"(r3) : "r"(a))
#define CP16(dst, src) \
    asm volatile("cp.async.cg.shared.global [%0], [%1], 16;" :: "r"(dst), "l"(src))
#define CPCOMMIT() asm volatile("cp.async.commit_group;")
#define CPWAITG(N) asm volatile("cp.async.wait_group %0;" :: "n"(N) : "memory")

__device__ __forceinline__ void split8(const float4 x, uint2& hi, uint2& lo) {
    __half h0 = __float2half_rn(x.x), h1 = __float2half_rn(x.y);
    __half h2 = __float2half_rn(x.z), h3 = __float2half_rn(x.w);
    __half e0 = __float2half_rn(x.x - __half2float(h0));
    __half e1 = __float2half_rn(x.y - __half2float(h1));
    __half e2 = __float2half_rn(x.z - __half2float(h2));
    __half e3 = __float2half_rn(x.w - __half2float(h3));
    __half2 a = __halves2half2(h0, h1), b = __halves2half2(h2, h3);
    __half2 c = __halves2half2(e0, e1), d = __halves2half2(e2, e3);
    hi.x = *(uint32_t*)&a; hi.y = *(uint32_t*)&b;
    lo.x = *(uint32_t*)&c; lo.y = *(uint32_t*)&d;
}

// attn smem (half-index offsets unless noted). Rows stride 72 halves.
#define SQH 0        // [64][72]
#define SQL 4608
#define SKB 9216     // 2 bufs x (KH 64x72 | KL 64x72) = 9216 halves each
#define SP  27648    // [64][72]
#define VBB 64512    // BYTE offset: V [256][64] halves, 128B rows, XOR-swizzled
#define FOFFB 97280  // BYTE offset of float region
#define RM 0
#define FF 128
#define LR 192
#define ATTN_SMEM (FOFFB + 320 * 4)   // 98,560 B -> 2 CTAs/SM

// ---------------------------------------------------------------------------
// conv q/k: fp16 3-pass GEMM (validated R8/R9)
// ---------------------------------------------------------------------------
__global__ __launch_bounds__(256)
void conv_qk_mma(const float* __restrict__ X, const float* __restrict__ W,
                 const float* __restrict__ bias, __half* __restrict__ Y,
                 int C, float scale) {
    __shared__ __half smc[13824];
    __shared__ float sbias[64];
    const int XL = 4352, WH = 8704, WL = 11264;
    const int b = blockIdx.z, n0 = blockIdx.x << 7;
    const int tid = threadIdx.x, lane = tid & 31, w = tid >> 5;
    const int gid = lane >> 2, tig = lane & 3, lr = lane & 15, lc = (lane >> 4) << 3;
    const uint32_t sb = smem_u32(smc);
    if (tid < 64) sbias[tid] = bias[tid];
    float acc[8][4];
    #pragma unroll
    for (int i = 0; i < 8; i++)
        #pragma unroll
        for (int e = 0; e < 4; e++) acc[i][e] = 0.f;

    for (int c0 = 0; c0 < C; c0 += 32) {
        __syncthreads();
        #pragma unroll
        for (int p = 0; p < 4; p++) {
            int idx = tid + p * 256, cc = idx >> 5, n4 = (idx & 31) << 2;
            float4 x = *reinterpret_cast<const float4*>(X + ((size_t)b * C + c0 + cc) * NTOK + n0 + n4);
            uint2 hi, lo; split8(x, hi, lo);
            *reinterpret_cast<uint2*>(smc + cc * 136 + n4) = hi;
            *reinterpret_cast<uint2*>(smc + XL + cc * 136 + n4) = lo;
        }
        #pragma unroll
        for (int p = 0; p < 2; p++) {
            int idx = tid + p * 256, oo = idx >> 3, c4 = (idx & 7) << 2;
            float4 x = *reinterpret_cast<const float4*>(W + (size_t)oo * C + c0 + c4);
            uint2 hi, lo; split8(x, hi, lo);
            *reinterpret_cast<uint2*>(smc + WH + oo * 40 + c4) = hi;
            *reinterpret_cast<uint2*>(smc + WL + oo * 40 + c4) = lo;
        }
        __syncthreads();
        #pragma unroll
        for (int ks = 0; ks < 2; ks++) {
            uint32_t ah0, ah1, ah2, ah3, al0, al1, al2, al3;
            uint32_t ax = sb + 2u * (((ks << 4) + (lane & 7) + ((lane >> 4) << 3)) * 136
                                     + (w << 4) + (((lane >> 3) & 1) << 3));
            LDSM4T(ah0, ah1, ah2, ah3, ax);
            LDSM4T(al0, al1, al2, al3, ax + 2u * XL);
            #pragma unroll
            for (int p = 0; p < 4; p++) {
                uint32_t bh0, bh1, bh2, bh3, bl0, bl1, bl2, bl3;
                uint32_t aw = sb + 2u * (WH + ((p << 4) + lr) * 40 + (ks << 4) + lc);
                LDSM4(bh0, bh1, bh2, bh3, aw);
                LDSM4(bl0, bl1, bl2, bl3, aw + 2u * (WL - WH));
                MMA16(acc[2 * p],     ah0, ah1, ah2, ah3, bh0, bh2);
                MMA16(acc[2 * p + 1], ah0, ah1, ah2, ah3, bh1, bh3);
                MMA16(acc[2 * p],     ah0, ah1, ah2, ah3, bl0, bl2);
                MMA16(acc[2 * p + 1], ah0, ah1, ah2, ah3, bl1, bl3);
                MMA16(acc[2 * p],     al0, al1, al2, al3, bh0, bh2);
                MMA16(acc[2 * p + 1], al0, al1, al2, al3, bh1, bh3);
            }
        }
    }
    const int tok0 = n0 + (w << 4) + gid;
    #pragma unroll
    for (int nt = 0; nt < 8; nt++) {
        const int c = nt * 8 + 2 * tig;
        float b0s = sbias[c], b1s = sbias[c + 1];
        #pragma unroll
        for (int rr = 0; rr < 2; rr++) {
            float v0 = (acc[nt][2 * rr] + b0s) * scale;
            float v1 = (acc[nt][2 * rr + 1] + b1s) * scale;
            __half h0 = __float2half_rn(v0), h1 = __float2half_rn(v1);
            __half2 hh = __halves2half2(h0, h1);
            __half2 ll = __halves2half2(__float2half_rn(v0 - __half2float(h0)),
                                        __float2half_rn(v1 - __half2float(h1)));
            __half* yp = Y + ((size_t)b * NTOK + tok0 + rr * 8) * 128 + c;
            *(uint32_t*)yp = *(uint32_t*)&hh;
            *(uint32_t*)(yp + 64) = *(uint32_t*)&ll;
        }
    }
}

// conv v: single-pass fp16 GEMM, tiled output (validated R8/R9)
__global__ __launch_bounds__(256)
void conv_v_mma(const float* __restrict__ X, const float* __restrict__ W,
                const float* __restrict__ bias, __half* __restrict__ Y, int C) {
    __shared__ __half smc[9472];
    __shared__ float sbias[128];
    const int WHo = 4352;
    const int b = blockIdx.z, o0 = blockIdx.y << 7, n0 = blockIdx.x << 7;
    const int tid = threadIdx.x, lane = tid & 31, w = tid >> 5;
    const int gid = lane >> 2, tig = lane & 3, lr = lane & 15, lc = (lane >> 4) << 3;
    const uint32_t sb = smem_u32(smc);
    if (tid < 128) sbias[tid] = bias[o0 + tid];
    float acc[16][4];
    #pragma unroll
    for (int i = 0; i < 16; i++)
        #pragma unroll
        for (int e = 0; e < 4; e++) acc[i][e] = 0.f;

    for (int c0 = 0; c0 < C; c0 += 32) {
        __syncthreads();
        #pragma unroll
        for (int p = 0; p < 4; p++) {
            int idx = tid + p * 256, cc = idx >> 5, n4 = (idx & 31) << 2;
            float4 x = *reinterpret_cast<const float4*>(X + ((size_t)b * C + c0 + cc) * NTOK + n0 + n4);
            __half2 p0 = __floats2half2_rn(x.x, x.y), p1 = __floats2half2_rn(x.z, x.w);
            uint2 u; u.x = *(uint32_t*)&p0; u.y = *(uint32_t*)&p1;
            *reinterpret_cast<uint2*>(smc + cc * 136 + n4) = u;
        }
        #pragma unroll
        for (int p = 0; p < 4; p++) {
            int idx = tid + p * 256, oo = idx >> 3, c4 = (idx & 7) << 2;
            float4 x = *reinterpret_cast<const float4*>(W + (size_t)(o0 + oo) * C + c0 + c4);
            __half2 p0 = __floats2half2_rn(x.x, x.y), p1 = __floats2half2_rn(x.z, x.w);
            uint2 u; u.x = *(uint32_t*)&p0; u.y = *(uint32_t*)&p1;
            *reinterpret_cast<uint2*>(smc + WHo + oo * 40 + c4) = u;
        }
        __syncthreads();
        #pragma unroll
        for (int ks = 0; ks < 2; ks++) {
            uint32_t a0, a1, a2, a3;
            LDSM4(a0, a1, a2, a3, sb + 2u * (WHo + ((w << 4) + lr) * 40 + (ks << 4) + lc));
            #pragma unroll
            for (int tp = 0; tp < 8; tp++) {
                uint32_t v0, v1, v2, v3;
                uint32_t ax = sb + 2u * (((ks << 4) + (lane & 7) + ((lane >> 4) << 3)) * 136
                                         + (tp << 4) + (((lane >> 3) & 1) << 3));
                LDSM4T(v0, v1, v2, v3, ax);
                MMA16(acc[2 * tp],     a0, a1, a2, a3, v0, v2);
                MMA16(acc[2 * tp + 1], a0, a1, a2, a3, v1, v3);
            }
        }
    }
    const int orow = (w << 4) + gid;
    float br0 = sbias[orow], br1 = sbias[orow + 8];
    __half* vbo = Y + ((size_t)b * NT + (n0 >> 6)) * CVCH * 64;
    #pragma unroll
    for (int nt = 0; nt < 16; nt++) {
        int tokoff = nt * 8 + 2 * tig;
        int tadd = tokoff >> 6, j = tokoff & 63;
        __half2 h0 = __floats2half2_rn(acc[nt][0] + br0, acc[nt][1] + br0);
        __half2 h1 = __floats2half2_rn(acc[nt][2] + br1, acc[nt][3] + br1);
        __half* p0 = vbo + ((size_t)tadd * CVCH + o0 + orow) * 64 + j;
        *(uint32_t*)p0 = *(uint32_t*)&h0;
        *(uint32_t*)(p0 + 8 * 64) = *(uint32_t*)&h1;
    }
}

// ---------------------------------------------------------------------------
// Flash attention (R9 structure): TQ=64, 256 thr, 2 CTAs/SM. K double-buffered,
// V single-buffered swizzled; split cp.async waits. R11: S-MMA pass-separated
// issue order (dep distance 4) + conditional O-rescale skip.
// ---------------------------------------------------------------------------
__global__ __launch_bounds__(256, 2)
void attn_kernel(const float* __restrict__ skip, const float* __restrict__ gamma,
                 float* __restrict__ out) {
    extern __shared__ __align__(16) char sm[];
    __half* smh = (__half*)sm;
    float* smf = (float*)(sm + FOFFB);
    const uint32_t sb = smem_u32(sm);
    const int tid = threadIdx.x, lane = tid & 31, w = tid >> 5;
    const int gid = lane >> 2, tig = lane & 3, lr = lane & 15, lc = (lane >> 4) << 3;
    const int r0 = (w & 3) << 4;            // S rows
    const int ch = w >> 2;                  // S col half (32 cols)
    const int rq = (w & 1) << 5, cq = (w >> 1) << 6;   // PV partition
    const int b = blockIdx.y, i0 = blockIdx.x * TQ;
    const int row0 = r0 + gid, row1 = row0 + 8;

    const __half* qb = g_q16 + (size_t)b * NTOK * 128;
    const __half* kb = g_k16 + (size_t)b * NTOK * 128;
    const __half* vbg = g_v16 + (size_t)b * NT * CVCH * TK;

    // prologue: group1 = Q, group2 = K(0)
    #pragma unroll
    for (int p = 0; p < 4; p++) {
        int chunk = tid + p * 256, row = chunk >> 4, c16 = chunk & 15;
        uint32_t d = sb + 2u * (c16 < 8 ? SQH + row * 72 + c16 * 8
                                        : SQL + row * 72 + (c16 - 8) * 8);
        CP16(d, qb + (size_t)(i0 + row) * 128 + c16 * 8);
    }
    CPCOMMIT();
    #pragma unroll
    for (int p = 0; p < 4; p++) {
        int chunk = tid + p * 256, row = chunk >> 4, c16 = chunk & 15;
        uint32_t d = sb + 2u * (c16 < 8 ? SKB + row * 72 + c16 * 8
                                        : SKB + 4608 + row * 72 + (c16 - 8) * 8);
        CP16(d, kb + (size_t)row * 128 + c16 * 8);
    }
    CPCOMMIT();

    float oacc[16][4];
    #pragma unroll
    for (int t = 0; t < 16; t++)
        #pragma unroll
        for (int e = 0; e < 4; e++) oacc[t][e] = 0.f;
    float rm0 = -1e30f, rm1 = -1e30f, lsum0 = 0.f, lsum1 = 0.f;

    for (int t = 0; t < NT; t++) {
        const int buf = t & 1;
        __syncthreads();   // PV(t-1) complete: vbuf + kbuf[(t+1)&1] free
        // issue V(t) (group), then K(t+1) (group)
        {
            const __half* vt = vbg + (size_t)t * CVCH * TK;
            #pragma unroll
            for (int p = 0; p < 8; p++) {
                int chunk = tid + p * 256, row = chunk >> 3, cb = chunk & 7;
                uint32_t d = sb + VBB + row * 128 + (((uint32_t)(cb ^ (row & 7))) << 4);
                CP16(d, vt + (size_t)row * 64 + cb * 8);
            }
            CPCOMMIT();
            const int tn = (t + 1) & (NT - 1);
            const int kbase = SKB + ((t + 1) & 1) * 9216;
            #pragma unroll
            for (int p = 0; p < 4; p++) {
                int chunk = tid + p * 256, row = chunk >> 4, c16 = chunk & 15;
                uint32_t d = sb + 2u * (c16 < 8 ? kbase + row * 72 + c16 * 8
                                                : kbase + 4608 + row * 72 + (c16 - 8) * 8);
                CP16(d, kb + (size_t)(tn * TK + row) * 128 + c16 * 8);
            }
            CPCOMMIT();
        }
        CPWAITG(2);        // K(t) (and Q) ready; V(t), K(t+1) may pend
        __syncthreads();

        // S = Q.K^T (fp16 3-pass), pass-separated: 4 independent acc chains
        const int kh = SKB + buf * 9216;
        float sacc[4][4];
        #pragma unroll
        for (int tt = 0; tt < 4; tt++)
            #pragma unroll
            for (int e = 0; e < 4; e++) sacc[tt][e] = 0.f;
        #pragma unroll
        for (int kk = 0; kk < 4; kk++) {
            uint32_t ah0, ah1, ah2, ah3, al0, al1, al2, al3;
            uint32_t aq = sb + 2u * (SQH + (r0 + lr) * 72 + kk * 16 + lc);
            LDSM4(ah0, ah1, ah2, ah3, aq);
            LDSM4(al0, al1, al2, al3, aq + 2u * SQL);
            uint32_t bh[2][4], bl[2][4];
            #pragma unroll
            for (int tp = 0; tp < 2; tp++) {
                uint32_t ak = sb + 2u * (kh + (ch * 32 + tp * 16 + lr) * 72 + kk * 16 + lc);
                LDSM4(bh[tp][0], bh[tp][1], bh[tp][2], bh[tp][3], ak);
                LDSM4(bl[tp][0], bl[tp][1], bl[tp][2], bl[tp][3], ak + 2u * 4608);
            }
            // pass 1: hi*hi (4 independent accumulators)
            MMA16(sacc[0], ah0, ah1, ah2, ah3, bh[0][0], bh[0][2]);
            MMA16(sacc[1], ah0, ah1, ah2, ah3, bh[0][1], bh[0][3]);
            MMA16(sacc[2], ah0, ah1, ah2, ah3, bh[1][0], bh[1][2]);
            MMA16(sacc[3], ah0, ah1, ah2, ah3, bh[1][1], bh[1][3]);
            // pass 2: hi*lo
            MMA16(sacc[0], ah0, ah1, ah2, ah3, bl[0][0], bl[0][2]);
            MMA16(sacc[1], ah0, ah1, ah2, ah3, bl[0][1], bl[0][3]);
            MMA16(sacc[2], ah0, ah1, ah2, ah3, bl[1][0], bl[1][2]);
            MMA16(sacc[3], ah0, ah1, ah2, ah3, bl[1][1], bl[1][3]);
            // pass 3: lo*hi
            MMA16(sacc[0], al0, al1, al2, al3, bh[0][0], bh[0][2]);
            MMA16(sacc[1], al0, al1, al2, al3, bh[0][1], bh[0][3]);
            MMA16(sacc[2], al0, al1, al2, al3, bh[1][0], bh[1][2]);
            MMA16(sacc[3], al0, al1, al2, al3, bh[1][1], bh[1][3]);
        }
        float mx0 = -1e30f, mx1 = -1e30f;
        #pragma unroll
        for (int tt = 0; tt < 4; tt++) {
            mx0 = fmaxf(mx0, fmaxf(sacc[tt][0], sacc[tt][1]));
            mx1 = fmaxf(mx1, fmaxf(sacc[tt][2], sacc[tt][3]));
        }
        mx0 = fmaxf(mx0, __shfl_xor_sync(0xFFFFFFFFu, mx0, 1));
        mx0 = fmaxf(mx0, __shfl_xor_sync(0xFFFFFFFFu, mx0, 2));
        mx1 = fmaxf(mx1, __shfl_xor_sync(0xFFFFFFFFu, mx1, 1));
        mx1 = fmaxf(mx1, __shfl_xor_sync(0xFFFFFFFFu, mx1, 2));
        if (tig == 0) {
            smf[RM + row0 * 2 + ch] = mx0;
            smf[RM + row1 * 2 + ch] = mx1;
        }
        __syncthreads();

        // online softmax -> P fp16
        float mn0 = fmaxf(rm0, fmaxf(smf[RM + row0 * 2], smf[RM + row0 * 2 + 1]));
        float mn1 = fmaxf(rm1, fmaxf(smf[RM + row1 * 2], smf[RM + row1 * 2 + 1]));
        float f0 = fast_exp2(rm0 - mn0), f1 = fast_exp2(rm1 - mn1);
        rm0 = mn0; rm1 = mn1;
        if (tig == 0 && ch == 0) { smf[FF + row0] = f0; smf[FF + row1] = f1; }
        float ps0 = 0.f, ps1 = 0.f;
        #pragma unroll
        for (int tt = 0; tt < 4; tt++) {
            float p00 = fast_exp2(sacc[tt][0] - mn0);
            float p01 = fast_exp2(sacc[tt][1] - mn0);
            float p10 = fast_exp2(sacc[tt][2] - mn1);
            float p11 = fast_exp2(sacc[tt][3] - mn1);
            ps0 += p00 + p01; ps1 += p10 + p11;
            __half2 h0 = __floats2half2_rn(p00, p01);
            __half2 h1 = __floats2half2_rn(p10, p11);
            const int cc = ch * 32 + tt * 8 + 2 * tig;
            *(uint32_t*)(smh + SP + row0 * 72 + cc) = *(uint32_t*)&h0;
            *(uint32_t*)(smh + SP + row1 * 72 + cc) = *(uint32_t*)&h1;
        }
        lsum0 = lsum0 * f0 + ps0;
        lsum1 = lsum1 * f1 + ps1;
        CPWAITG(1);        // V(t) ready; K(t+1) may pend
        __syncthreads();   // P + V visible

        // rescale O (skipped when no row max changed), then O += P.V^T
        float fa0 = smf[FF + rq + gid], fa1 = smf[FF + rq + gid + 8];
        float fb0 = smf[FF + rq + 16 + gid], fb1 = smf[FF + rq + 16 + gid + 8];
        if (!__all_sync(0xFFFFFFFFu,
                        (fa0 == 1.f) & (fa1 == 1.f) & (fb0 == 1.f) & (fb1 == 1.f))) {
            #pragma unroll
            for (int nt = 0; nt < 8; nt++) {
                oacc[nt][0] *= fa0; oacc[nt][1] *= fa0;
                oacc[nt][2] *= fa1; oacc[nt][3] *= fa1;
                oacc[8 + nt][0] *= fb0; oacc[8 + nt][1] *= fb0;
                oacc[8 + nt][2] *= fb1; oacc[8 + nt][3] *= fb1;
            }
        }
        #pragma unroll
        for (int kk = 0; kk < 4; kk++) {
            uint32_t pa0, pa1, pa2, pa3, qa0, qa1, qa2, qa3;
            uint32_t ap = sb + 2u * (SP + (rq + lr) * 72 + kk * 16 + lc);
            LDSM4(pa0, pa1, pa2, pa3, ap);
            LDSM4(qa0, qa1, qa2, qa3, ap + 2u * (16 * 72));
            const uint32_t cb = (uint32_t)(kk * 2 + (lc >> 3));
            #pragma unroll
            for (int np = 0; np < 4; np++) {
                const int vrow = cq + np * 16 + lr;
                uint32_t va = sb + VBB + vrow * 128 + ((cb ^ (uint32_t)(vrow & 7)) << 4);
                uint32_t v0, v1, v2, v3;
                LDSM4(v0, v1, v2, v3, va);
                MMA16(oacc[2 * np],         pa0, pa1, pa2, pa3, v0, v2);
                MMA16(oacc[2 * np + 1],     pa0, pa1, pa2, pa3, v1, v3);
                MMA16(oacc[8 + 2 * np],     qa0, qa1, qa2, qa3, v0, v2);
                MMA16(oacc[8 + 2 * np + 1], qa0, qa1, qa2, qa3, v1, v3);
            }
        }
    }

    // final l reduction + epilogue
    lsum0 += __shfl_xor_sync(0xFFFFFFFFu, lsum0, 1);
    lsum0 += __shfl_xor_sync(0xFFFFFFFFu, lsum0, 2);
    lsum1 += __shfl_xor_sync(0xFFFFFFFFu, lsum1, 1);
    lsum1 += __shfl_xor_sync(0xFFFFFFFFu, lsum1, 2);
    __syncthreads();
    if (tig == 0) {
        smf[LR + row0 * 2 + ch] = lsum0;
        smf[LR + row1 * 2 + ch] = lsum1;
    }
    __syncthreads();

    const float gm = __ldg(gamma);
    const float* skb = skip + (size_t)b * CVCH * NTOK;
    float* ob = out + (size_t)b * CVCH * NTOK;
    #pragma unroll
    for (int mt = 0; mt < 2; mt++) {
        const int ra = rq + mt * 16 + gid, rb = ra + 8;
        const float fca = gm / (smf[LR + ra * 2] + smf[LR + ra * 2 + 1]);
        const float fcb = gm / (smf[LR + rb * 2] + smf[LR + rb * 2 + 1]);
        const int ia = i0 + ra, ib = i0 + rb;
        #pragma unroll
        for (int nt = 0; nt < 8; nt++) {
            const int c = cq + nt * 8 + 2 * tig;
            const size_t oA = (size_t)c * NTOK, oB = (size_t)(c + 1) * NTOK;
            const float* acc = oacc[mt * 8 + nt];
            ob[oA + ia] = acc[0] * fca + skb[oA + ia];
            ob[oB + ia] = acc[1] * fca + skb[oB + ia];
            ob[oA + ib] = acc[2] * fcb + skb[oA + ib];
            ob[oB + ib] = acc[3] * fcb + skb[oB + ib];
        }
    }
}

// ---------------------------------------------------------------------------
static __half* s_q = nullptr;
static __half* s_k = nullptr;
static __half* s_v = nullptr;

extern "C" void kernel_launch(void* const* d_in, const int* in_sizes, int n_in,
                              void* d_out, int out_size) {
    (void)in_sizes; (void)n_in; (void)out_size;
    static bool initialized = []() {
        void* p;
        cudaGetSymbolAddress(&p, g_q16); s_q = (__half*)p;
        cudaGetSymbolAddress(&p, g_k16); s_k = (__half*)p;
        cudaGetSymbolAddress(&p, g_v16); s_v = (__half*)p;
        cudaFuncSetAttribute(attn_kernel, cudaFuncAttributeMaxDynamicSharedMemorySize,
                             ATTN_SMEM);
        return true;
    }();
    (void)initialized;

    const float* gate  = (const float*)d_in[0];
    const float* skip  = (const float*)d_in[1];
    const float* Wq    = (const float*)d_in[2];
    const float* bq    = (const float*)d_in[3];
    const float* Wk    = (const float*)d_in[4];
    const float* bk    = (const float*)d_in[5];
    const float* Wv    = (const float*)d_in[6];
    const float* bv    = (const float*)d_in[7];
    const float* gamma = (const float*)d_in[8];
    float* out = (float*)d_out;

    const float LOG2E = 1.4426950408889634f;

    conv_qk_mma<<<dim3(32, 1, NB), 256>>>(gate, Wq, bq, s_q, 512, LOG2E);
    conv_qk_mma<<<dim3(32, 1, NB), 256>>>(skip, Wk, bk, s_k, 256, 1.0f);
    conv_v_mma <<<dim3(32, 2, NB), 256>>>(skip, Wv, bv, s_v, 256);
    attn_kernel<<<dim3(NTOK / TQ, NB), 256, ATTN_SMEM>>>(skip, gamma, out);
}

// round 12
// speedup vs baseline: 1.1271x; 1.0748x over previous
#include <cuda_runtime.h>
#include <cuda_fp16.h>
#include <cstdint>
#include <cstddef>

#define NTOK 4096
#define DQK  64
#define CVCH 256
#define NB   4
#define TQ   64
#define TK   64
#define NT   (NTOK / TK)   // 64

__device__ __align__(16) __half g_q16[NB * NTOK * 128];     // [b][n][hi64|lo64]
__device__ __align__(16) __half g_k16[NB * NTOK * 128];
__device__ __align__(16) __half g_v16[NB * NT * CVCH * TK]; // [b][t][c][64j]

__device__ __forceinline__ float fast_exp2(float x) {
    float r; asm("ex2.approx.ftz.f32 %0, %1;" : "=f"(r) : "f"(x)); return r;
}
__device__ __forceinline__ uint32_t smem_u32(const void* p) {
    uint32_t a;
    asm("{ .reg .u64 t; cvta.to.shared.u64 t, %1; cvt.u32.u64 %0, t; }" : "=r"(a) : "l"(p));
    return a;
}
#define MMA16(d, a0, a1, a2, a3, b0, b1) \
    asm volatile("mma.sync.aligned.m16n8k16.row.col.f32.f16.f16.f32 " \
        "{%0,%1,%2,%3}, {%4,%5,%6,%7}, {%8,%9}, {%0,%1,%2,%3};" \
        : "+f"((d)[0]), "+f"((d)[1]), "+f"((d)[2]), "+f"((d)[3]) \
        : "r"(a0), "r"(a1), "r"(a2), "r"(a3), "r"(b0), "r"(b1))
#define LDSM4(r0, r1, r2, r3, a) \
    asm volatile("ldmatrix.sync.aligned.m8n8.x4.shared.b16 {%0,%1,%2,%3},[%4];" \
        : "=r"(r0), "=r"(r1), "=r"(r2), "=r"(r3) : "r"(a))
#define LDSM4T(r0, r1, r2, r3, a) \
    asm volatile("ldmatrix.sync.aligned.m8n8.x4.trans.shared.b16 {%0,%1,%2,%3},[%4];" \
        : "=r"(r0), "=r"(r1), "=r"(r2), "=r"(r3) : "r"(a))
#define CP16(dst, src) \
    asm volatile("cp.async.cg.shared.global [%0], [%1], 16;" :: "r"(dst), "l"(src))
#define CPCOMMIT() asm volatile("cp.async.commit_group;")
#define CPWAITG(N) asm volatile("cp.async.wait_group %0;" :: "n"(N) : "memory")

__device__ __forceinline__ void split8(const float4 x, uint2& hi, uint2& lo) {
    __half h0 = __float2half_rn(x.x), h1 = __float2half_rn(x.y);
    __half h2 = __float2half_rn(x.z), h3 = __float2half_rn(x.w);
    __half e0 = __float2half_rn(x.x - __half2float(h0));
    __half e1 = __float2half_rn(x.y - __half2float(h1));
    __half e2 = __float2half_rn(x.z - __half2float(h2));
    __half e3 = __float2half_rn(x.w - __half2float(h3));
    __half2 a = __halves2half2(h0, h1), b = __halves2half2(h2, h3);
    __half2 c = __halves2half2(e0, e1), d = __halves2half2(e2, e3);
    hi.x = *(uint32_t*)&a; hi.y = *(uint32_t*)&b;
    lo.x = *(uint32_t*)&c; lo.y = *(uint32_t*)&d;
}

// attn smem (half-index offsets unless noted). Rows stride 72 halves.
#define SQH 0        // [64][72]
#define SQL 4608
#define SKB 9216     // 2 bufs x (KH 64x72 | KL 64x72) = 9216 halves each
#define SP  27648    // [64][72]
#define VBB 64512    // BYTE offset: V [256][64] halves, 128B rows, XOR-swizzled
#define FOFFB 97280  // BYTE offset of float region
#define RM 0
#define FF 128
#define LR 192
#define ATTN_SMEM (FOFFB + 320 * 4)   // 98,560 B -> 2 CTAs/SM

// ---------------------------------------------------------------------------
// conv bodies (validated R8-R11), as device functions over shared buffers.
// ---------------------------------------------------------------------------
__device__ __forceinline__
void conv_qk_body(__half* smc, float* sbias, const float* __restrict__ X,
                  const float* __restrict__ W, const float* __restrict__ bias,
                  __half* __restrict__ Y, int C, float scale, int b, int n0) {
    const int XL = 4352, WH = 8704, WL = 11264;
    const int tid = threadIdx.x, lane = tid & 31, w = tid >> 5;
    const int gid = lane >> 2, tig = lane & 3, lr = lane & 15, lc = (lane >> 4) << 3;
    const uint32_t sb = smem_u32(smc);
    if (tid < 64) sbias[tid] = bias[tid];
    float acc[8][4];
    #pragma unroll
    for (int i = 0; i < 8; i++)
        #pragma unroll
        for (int e = 0; e < 4; e++) acc[i][e] = 0.f;

    for (int c0 = 0; c0 < C; c0 += 32) {
        __syncthreads();
        #pragma unroll
        for (int p = 0; p < 4; p++) {
            int idx = tid + p * 256, cc = idx >> 5, n4 = (idx & 31) << 2;
            float4 x = *reinterpret_cast<const float4*>(X + ((size_t)b * C + c0 + cc) * NTOK + n0 + n4);
            uint2 hi, lo; split8(x, hi, lo);
            *reinterpret_cast<uint2*>(smc + cc * 136 + n4) = hi;
            *reinterpret_cast<uint2*>(smc + XL + cc * 136 + n4) = lo;
        }
        #pragma unroll
        for (int p = 0; p < 2; p++) {
            int idx = tid + p * 256, oo = idx >> 3, c4 = (idx & 7) << 2;
            float4 x = *reinterpret_cast<const float4*>(W + (size_t)oo * C + c0 + c4);
            uint2 hi, lo; split8(x, hi, lo);
            *reinterpret_cast<uint2*>(smc + WH + oo * 40 + c4) = hi;
            *reinterpret_cast<uint2*>(smc + WL + oo * 40 + c4) = lo;
        }
        __syncthreads();
        #pragma unroll
        for (int ks = 0; ks < 2; ks++) {
            uint32_t ah0, ah1, ah2, ah3, al0, al1, al2, al3;
            uint32_t ax = sb + 2u * (((ks << 4) + (lane & 7) + ((lane >> 4) << 3)) * 136
                                     + (w << 4) + (((lane >> 3) & 1) << 3));
            LDSM4T(ah0, ah1, ah2, ah3, ax);
            LDSM4T(al0, al1, al2, al3, ax + 2u * XL);
            #pragma unroll
            for (int p = 0; p < 4; p++) {
                uint32_t bh0, bh1, bh2, bh3, bl0, bl1, bl2, bl3;
                uint32_t aw = sb + 2u * (WH + ((p << 4) + lr) * 40 + (ks << 4) + lc);
                LDSM4(bh0, bh1, bh2, bh3, aw);
                LDSM4(bl0, bl1, bl2, bl3, aw + 2u * (WL - WH));
                MMA16(acc[2 * p],     ah0, ah1, ah2, ah3, bh0, bh2);
                MMA16(acc[2 * p + 1], ah0, ah1, ah2, ah3, bh1, bh3);
                MMA16(acc[2 * p],     ah0, ah1, ah2, ah3, bl0, bl2);
                MMA16(acc[2 * p + 1], ah0, ah1, ah2, ah3, bl1, bl3);
                MMA16(acc[2 * p],     al0, al1, al2, al3, bh0, bh2);
                MMA16(acc[2 * p + 1], al0, al1, al2, al3, bh1, bh3);
            }
        }
    }
    const int tok0 = n0 + (w << 4) + gid;
    #pragma unroll
    for (int nt = 0; nt < 8; nt++) {
        const int c = nt * 8 + 2 * tig;
        float b0s = sbias[c], b1s = sbias[c + 1];
        #pragma unroll
        for (int rr = 0; rr < 2; rr++) {
            float v0 = (acc[nt][2 * rr] + b0s) * scale;
            float v1 = (acc[nt][2 * rr + 1] + b1s) * scale;
            __half h0 = __float2half_rn(v0), h1 = __float2half_rn(v1);
            __half2 hh = __halves2half2(h0, h1);
            __half2 ll = __halves2half2(__float2half_rn(v0 - __half2float(h0)),
                                        __float2half_rn(v1 - __half2float(h1)));
            __half* yp = Y + ((size_t)b * NTOK + tok0 + rr * 8) * 128 + c;
            *(uint32_t*)yp = *(uint32_t*)&hh;
            *(uint32_t*)(yp + 64) = *(uint32_t*)&ll;
        }
    }
}

__device__ __forceinline__
void conv_v_body(__half* smc, float* sbias, const float* __restrict__ X,
                 const float* __restrict__ W, const float* __restrict__ bias,
                 __half* __restrict__ Y, int C, int b, int o0, int n0) {
    const int WHo = 4352;
    const int tid = threadIdx.x, lane = tid & 31, w = tid >> 5;
    const int gid = lane >> 2, tig = lane & 3, lr = lane & 15, lc = (lane >> 4) << 3;
    const uint32_t sb = smem_u32(smc);
    if (tid < 128) sbias[tid] = bias[o0 + tid];
    float acc[16][4];
    #pragma unroll
    for (int i = 0; i < 16; i++)
        #pragma unroll
        for (int e = 0; e < 4; e++) acc[i][e] = 0.f;

    for (int c0 = 0; c0 < C; c0 += 32) {
        __syncthreads();
        #pragma unroll
        for (int p = 0; p < 4; p++) {
            int idx = tid + p * 256, cc = idx >> 5, n4 = (idx & 31) << 2;
            float4 x = *reinterpret_cast<const float4*>(X + ((size_t)b * C + c0 + cc) * NTOK + n0 + n4);
            __half2 p0 = __floats2half2_rn(x.x, x.y), p1 = __floats2half2_rn(x.z, x.w);
            uint2 u; u.x = *(uint32_t*)&p0; u.y = *(uint32_t*)&p1;
            *reinterpret_cast<uint2*>(smc + cc * 136 + n4) = u;
        }
        #pragma unroll
        for (int p = 0; p < 4; p++) {
            int idx = tid + p * 256, oo = idx >> 3, c4 = (idx & 7) << 2;
            float4 x = *reinterpret_cast<const float4*>(W + (size_t)(o0 + oo) * C + c0 + c4);
            __half2 p0 = __floats2half2_rn(x.x, x.y), p1 = __floats2half2_rn(x.z, x.w);
            uint2 u; u.x = *(uint32_t*)&p0; u.y = *(uint32_t*)&p1;
            *reinterpret_cast<uint2*>(smc + WHo + oo * 40 + c4) = u;
        }
        __syncthreads();
        #pragma unroll
        for (int ks = 0; ks < 2; ks++) {
            uint32_t a0, a1, a2, a3;
            LDSM4(a0, a1, a2, a3, sb + 2u * (WHo + ((w << 4) + lr) * 40 + (ks << 4) + lc));
            #pragma unroll
            for (int tp = 0; tp < 8; tp++) {
                uint32_t v0, v1, v2, v3;
                uint32_t ax = sb + 2u * (((ks << 4) + (lane & 7) + ((lane >> 4) << 3)) * 136
                                         + (tp << 4) + (((lane >> 3) & 1) << 3));
                LDSM4T(v0, v1, v2, v3, ax);
                MMA16(acc[2 * tp],     a0, a1, a2, a3, v0, v2);
                MMA16(acc[2 * tp + 1], a0, a1, a2, a3, v1, v3);
            }
        }
    }
    const int orow = (w << 4) + gid;
    float br0 = sbias[orow], br1 = sbias[orow + 8];
    __half* vbo = Y + ((size_t)b * NT + (n0 >> 6)) * CVCH * 64;
    #pragma unroll
    for (int nt = 0; nt < 16; nt++) {
        int tokoff = nt * 8 + 2 * tig;
        int tadd = tokoff >> 6, j = tokoff & 63;
        __half2 h0 = __floats2half2_rn(acc[nt][0] + br0, acc[nt][1] + br0);
        __half2 h1 = __floats2half2_rn(acc[nt][2] + br1, acc[nt][3] + br1);
        __half* p0 = vbo + ((size_t)tadd * CVCH + o0 + orow) * 64 + j;
        *(uint32_t*)p0 = *(uint32_t*)&h0;
        *(uint32_t*)(p0 + 8 * 64) = *(uint32_t*)&h1;
    }
}

// One launch for all three convs: gx 0-31 q, 32-63 k, 64-127 v.
__global__ __launch_bounds__(256)
void fused_conv(const float* __restrict__ gate, const float* __restrict__ skip,
                const float* __restrict__ Wq, const float* __restrict__ bq,
                const float* __restrict__ Wk, const float* __restrict__ bk,
                const float* __restrict__ Wv, const float* __restrict__ bv,
                __half* __restrict__ q, __half* __restrict__ k,
                __half* __restrict__ v, float scale) {
    __shared__ __half smc[13824];
    __shared__ float sbias[128];
    const int gx = blockIdx.x, b = blockIdx.z;
    if (gx < 32) {
        conv_qk_body(smc, sbias, gate, Wq, bq, q, 512, scale, b, gx << 7);
    } else if (gx < 64) {
        conv_qk_body(smc, sbias, skip, Wk, bk, k, 256, 1.0f, b, (gx - 32) << 7);
    } else {
        const int vx = gx - 64;
        conv_v_body(smc, sbias, skip, Wv, bv, v, 256, b,
                    (vx >> 5) << 7, (vx & 31) << 7);
    }
}

// ---------------------------------------------------------------------------
// Flash attention — IDENTICAL to R11 (best measured 249.9 us).
// ---------------------------------------------------------------------------
__global__ __launch_bounds__(256, 2)
void attn_kernel(const float* __restrict__ skip, const float* __restrict__ gamma,
                 float* __restrict__ out) {
    extern __shared__ __align__(16) char sm[];
    __half* smh = (__half*)sm;
    float* smf = (float*)(sm + FOFFB);
    const uint32_t sb = smem_u32(sm);
    const int tid = threadIdx.x, lane = tid & 31, w = tid >> 5;
    const int gid = lane >> 2, tig = lane & 3, lr = lane & 15, lc = (lane >> 4) << 3;
    const int r0 = (w & 3) << 4;
    const int ch = w >> 2;
    const int rq = (w & 1) << 5, cq = (w >> 1) << 6;
    const int b = blockIdx.y, i0 = blockIdx.x * TQ;
    const int row0 = r0 + gid, row1 = row0 + 8;

    const __half* qb = g_q16 + (size_t)b * NTOK * 128;
    const __half* kb = g_k16 + (size_t)b * NTOK * 128;
    const __half* vbg = g_v16 + (size_t)b * NT * CVCH * TK;

    #pragma unroll
    for (int p = 0; p < 4; p++) {
        int chunk = tid + p * 256, row = chunk >> 4, c16 = chunk & 15;
        uint32_t d = sb + 2u * (c16 < 8 ? SQH + row * 72 + c16 * 8
                                        : SQL + row * 72 + (c16 - 8) * 8);
        CP16(d, qb + (size_t)(i0 + row) * 128 + c16 * 8);
    }
    CPCOMMIT();
    #pragma unroll
    for (int p = 0; p < 4; p++) {
        int chunk = tid + p * 256, row = chunk >> 4, c16 = chunk & 15;
        uint32_t d = sb + 2u * (c16 < 8 ? SKB + row * 72 + c16 * 8
                                        : SKB + 4608 + row * 72 + (c16 - 8) * 8);
        CP16(d, kb + (size_t)row * 128 + c16 * 8);
    }
    CPCOMMIT();

    float oacc[16][4];
    #pragma unroll
    for (int t = 0; t < 16; t++)
        #pragma unroll
        for (int e = 0; e < 4; e++) oacc[t][e] = 0.f;
    float rm0 = -1e30f, rm1 = -1e30f, lsum0 = 0.f, lsum1 = 0.f;

    for (int t = 0; t < NT; t++) {
        const int buf = t & 1;
        __syncthreads();
        {
            const __half* vt = vbg + (size_t)t * CVCH * TK;
            #pragma unroll
            for (int p = 0; p < 8; p++) {
                int chunk = tid + p * 256, row = chunk >> 3, cb = chunk & 7;
                uint32_t d = sb + VBB + row * 128 + (((uint32_t)(cb ^ (row & 7))) << 4);
                CP16(d, vt + (size_t)row * 64 + cb * 8);
            }
            CPCOMMIT();
            const int tn = (t + 1) & (NT - 1);
            const int kbase = SKB + ((t + 1) & 1) * 9216;
            #pragma unroll
            for (int p = 0; p < 4; p++) {
                int chunk = tid + p * 256, row = chunk >> 4, c16 = chunk & 15;
                uint32_t d = sb + 2u * (c16 < 8 ? kbase + row * 72 + c16 * 8
                                                : kbase + 4608 + row * 72 + (c16 - 8) * 8);
                CP16(d, kb + (size_t)(tn * TK + row) * 128 + c16 * 8);
            }
            CPCOMMIT();
        }
        CPWAITG(2);
        __syncthreads();

        const int kh = SKB + buf * 9216;
        float sacc[4][4];
        #pragma unroll
        for (int tt = 0; tt < 4; tt++)
            #pragma unroll
            for (int e = 0; e < 4; e++) sacc[tt][e] = 0.f;
        #pragma unroll
        for (int kk = 0; kk < 4; kk++) {
            uint32_t ah0, ah1, ah2, ah3, al0, al1, al2, al3;
            uint32_t aq = sb + 2u * (SQH + (r0 + lr) * 72 + kk * 16 + lc);
            LDSM4(ah0, ah1, ah2, ah3, aq);
            LDSM4(al0, al1, al2, al3, aq + 2u * SQL);
            uint32_t bh[2][4], bl[2][4];
            #pragma unroll
            for (int tp = 0; tp < 2; tp++) {
                uint32_t ak = sb + 2u * (kh + (ch * 32 + tp * 16 + lr) * 72 + kk * 16 + lc);
                LDSM4(bh[tp][0], bh[tp][1], bh[tp][2], bh[tp][3], ak);
                LDSM4(bl[tp][0], bl[tp][1], bl[tp][2], bl[tp][3], ak + 2u * 4608);
            }
            MMA16(sacc[0], ah0, ah1, ah2, ah3, bh[0][0], bh[0][2]);
            MMA16(sacc[1], ah0, ah1, ah2, ah3, bh[0][1], bh[0][3]);
            MMA16(sacc[2], ah0, ah1, ah2, ah3, bh[1][0], bh[1][2]);
            MMA16(sacc[3], ah0, ah1, ah2, ah3, bh[1][1], bh[1][3]);
            MMA16(sacc[0], ah0, ah1, ah2, ah3, bl[0][0], bl[0][2]);
            MMA16(sacc[1], ah0, ah1, ah2, ah3, bl[0][1], bl[0][3]);
            MMA16(sacc[2], ah0, ah1, ah2, ah3, bl[1][0], bl[1][2]);
            MMA16(sacc[3], ah0, ah1, ah2, ah3, bl[1][1], bl[1][3]);
            MMA16(sacc[0], al0, al1, al2, al3, bh[0][0], bh[0][2]);
            MMA16(sacc[1], al0, al1, al2, al3, bh[0][1], bh[0][3]);
            MMA16(sacc[2], al0, al1, al2, al3, bh[1][0], bh[1][2]);
            MMA16(sacc[3], al0, al1, al2, al3, bh[1][1], bh[1][3]);
        }
        float mx0 = -1e30f, mx1 = -1e30f;
        #pragma unroll
        for (int tt = 0; tt < 4; tt++) {
            mx0 = fmaxf(mx0, fmaxf(sacc[tt][0], sacc[tt][1]));
            mx1 = fmaxf(mx1, fmaxf(sacc[tt][2], sacc[tt][3]));
        }
        mx0 = fmaxf(mx0, __shfl_xor_sync(0xFFFFFFFFu, mx0, 1));
        mx0 = fmaxf(mx0, __shfl_xor_sync(0xFFFFFFFFu, mx0, 2));
        mx1 = fmaxf(mx1, __shfl_xor_sync(0xFFFFFFFFu, mx1, 1));
        mx1 = fmaxf(mx1, __shfl_xor_sync(0xFFFFFFFFu, mx1, 2));
        if (tig == 0) {
            smf[RM + row0 * 2 + ch] = mx0;
            smf[RM + row1 * 2 + ch] = mx1;
        }
        __syncthreads();

        float mn0 = fmaxf(rm0, fmaxf(smf[RM + row0 * 2], smf[RM + row0 * 2 + 1]));
        float mn1 = fmaxf(rm1, fmaxf(smf[RM + row1 * 2], smf[RM + row1 * 2 + 1]));
        float f0 = fast_exp2(rm0 - mn0), f1 = fast_exp2(rm1 - mn1);
        rm0 = mn0; rm1 = mn1;
        if (tig == 0 && ch == 0) { smf[FF + row0] = f0; smf[FF + row1] = f1; }
        float ps0 = 0.f, ps1 = 0.f;
        #pragma unroll
        for (int tt = 0; tt < 4; tt++) {
            float p00 = fast_exp2(sacc[tt][0] - mn0);
            float p01 = fast_exp2(sacc[tt][1] - mn0);
            float p10 = fast_exp2(sacc[tt][2] - mn1);
            float p11 = fast_exp2(sacc[tt][3] - mn1);
            ps0 += p00 + p01; ps1 += p10 + p11;
            __half2 h0 = __floats2half2_rn(p00, p01);
            __half2 h1 = __floats2half2_rn(p10, p11);
            const int cc = ch * 32 + tt * 8 + 2 * tig;
            *(uint32_t*)(smh + SP + row0 * 72 + cc) = *(uint32_t*)&h0;
            *(uint32_t*)(smh + SP + row1 * 72 + cc) = *(uint32_t*)&h1;
        }
        lsum0 = lsum0 * f0 + ps0;
        lsum1 = lsum1 * f1 + ps1;
        CPWAITG(1);
        __syncthreads();

        float fa0 = smf[FF + rq + gid], fa1 = smf[FF + rq + gid + 8];
        float fb0 = smf[FF + rq + 16 + gid], fb1 = smf[FF + rq + 16 + gid + 8];
        if (!__all_sync(0xFFFFFFFFu,
                        (fa0 == 1.f) & (fa1 == 1.f) & (fb0 == 1.f) & (fb1 == 1.f))) {
            #pragma unroll
            for (int nt = 0; nt < 8; nt++) {
                oacc[nt][0] *= fa0; oacc[nt][1] *= fa0;
                oacc[nt][2] *= fa1; oacc[nt][3] *= fa1;
                oacc[8 + nt][0] *= fb0; oacc[8 + nt][1] *= fb0;
                oacc[8 + nt][2] *= fb1; oacc[8 + nt][3] *= fb1;
            }
        }
        #pragma unroll
        for (int kk = 0; kk < 4; kk++) {
            uint32_t pa0, pa1, pa2, pa3, qa0, qa1, qa2, qa3;
            uint32_t ap = sb + 2u * (SP + (rq + lr) * 72 + kk * 16 + lc);
            LDSM4(pa0, pa1, pa2, pa3, ap);
            LDSM4(qa0, qa1, qa2, qa3, ap + 2u * (16 * 72));
            const uint32_t cb = (uint32_t)(kk * 2 + (lc >> 3));
            #pragma unroll
            for (int np = 0; np < 4; np++) {
                const int vrow = cq + np * 16 + lr;
                uint32_t va = sb + VBB + vrow * 128 + ((cb ^ (uint32_t)(vrow & 7)) << 4);
                uint32_t v0, v1, v2, v3;
                LDSM4(v0, v1, v2, v3, va);
                MMA16(oacc[2 * np],         pa0, pa1, pa2, pa3, v0, v2);
                MMA16(oacc[2 * np + 1],     pa0, pa1, pa2, pa3, v1, v3);
                MMA16(oacc[8 + 2 * np],     qa0, qa1, qa2, qa3, v0, v2);
                MMA16(oacc[8 + 2 * np + 1], qa0, qa1, qa2, qa3, v1, v3);
            }
        }
    }

    lsum0 += __shfl_xor_sync(0xFFFFFFFFu, lsum0, 1);
    lsum0 += __shfl_xor_sync(0xFFFFFFFFu, lsum0, 2);
    lsum1 += __shfl_xor_sync(0xFFFFFFFFu, lsum1, 1);
    lsum1 += __shfl_xor_sync(0xFFFFFFFFu, lsum1, 2);
    __syncthreads();
    if (tig == 0) {
        smf[LR + row0 * 2 + ch] = lsum0;
        smf[LR + row1 * 2 + ch] = lsum1;
    }
    __syncthreads();

    const float gm = __ldg(gamma);
    const float* skb = skip + (size_t)b * CVCH * NTOK;
    float* ob = out + (size_t)b * CVCH * NTOK;
    #pragma unroll
    for (int mt = 0; mt < 2; mt++) {
        const int ra = rq + mt * 16 + gid, rb = ra + 8;
        const float fca = gm / (smf[LR + ra * 2] + smf[LR + ra * 2 + 1]);
        const float fcb = gm / (smf[LR + rb * 2] + smf[LR + rb * 2 + 1]);
        const int ia = i0 + ra, ib = i0 + rb;
        #pragma unroll
        for (int nt = 0; nt < 8; nt++) {
            const int c = cq + nt * 8 + 2 * tig;
            const size_t oA = (size_t)c * NTOK, oB = (size_t)(c + 1) * NTOK;
            const float* acc = oacc[mt * 8 + nt];
            ob[oA + ia] = acc[0] * fca + skb[oA + ia];
            ob[oB + ia] = acc[1] * fca + skb[oB + ia];
            ob[oA + ib] = acc[2] * fcb + skb[oA + ib];
            ob[oB + ib] = acc[3] * fcb + skb[oB + ib];
        }
    }
}

// ---------------------------------------------------------------------------
static __half* s_q = nullptr;
static __half* s_k = nullptr;
static __half* s_v = nullptr;

extern "C" void kernel_launch(void* const* d_in, const int* in_sizes, int n_in,
                              void* d_out, int out_size) {
    (void)in_sizes; (void)n_in; (void)out_size;
    static bool initialized = []() {
        void* p;
        cudaGetSymbolAddress(&p, g_q16); s_q = (__half*)p;
        cudaGetSymbolAddress(&p, g_k16); s_k = (__half*)p;
        cudaGetSymbolAddress(&p, g_v16); s_v = (__half*)p;
        cudaFuncSetAttribute(attn_kernel, cudaFuncAttributeMaxDynamicSharedMemorySize,
                             ATTN_SMEM);
        return true;
    }();
    (void)initialized;

    const float* gate  = (const float*)d_in[0];
    const float* skip  = (const float*)d_in[1];
    const float* Wq    = (const float*)d_in[2];
    const float* bq    = (const float*)d_in[3];
    const float* Wk    = (const float*)d_in[4];
    const float* bk    = (const float*)d_in[5];
    const float* Wv    = (const float*)d_in[6];
    const float* bv    = (const float*)d_in[7];
    const float* gamma = (const float*)d_in[8];
    float* out = (float*)d_out;

    const float LOG2E = 1.4426950408889634f;

    fused_conv<<<dim3(128, 1, NB), 256>>>(gate, skip, Wq, bq, Wk, bk, Wv, bv,
                                          s_q, s_k, s_v, LOG2E);
    attn_kernel<<<dim3(NTOK / TQ, NB), 256, ATTN_SMEM>>>(skip, gamma, out);
}

// round 13
// speedup vs baseline: 1.2624x; 1.1201x over previous
#include <cuda_runtime.h>
#include <cuda_fp16.h>
#include <cstdint>
#include <cstddef>

#define NTOK 4096
#define DQK  64
#define CVCH 256
#define NB   4
#define TQ   64
#define TK   64
#define NT   (NTOK / TK)   // 64

__device__ __align__(16) __half g_q16[NB * NTOK * 128];     // [b][n][hi64|lo64]
__device__ __align__(16) __half g_k16[NB * NTOK * 128];
__device__ __align__(16) __half g_v16[NB * NT * CVCH * TK]; // [b][t][c][64j]

__device__ __forceinline__ float fast_exp2(float x) {
    float r; asm("ex2.approx.ftz.f32 %0, %1;" : "=f"(r) : "f"(x)); return r;
}
__device__ __forceinline__ uint32_t smem_u32(const void* p) {
    uint32_t a;
    asm("{ .reg .u64 t; cvta.to.shared.u64 t, %1; cvt.u32.u64 %0, t; }" : "=r"(a) : "l"(p));
    return a;
}
#define MMA16(d, a0, a1, a2, a3, b0, b1) \
    asm volatile("mma.sync.aligned.m16n8k16.row.col.f32.f16.f16.f32 " \
        "{%0,%1,%2,%3}, {%4,%5,%6,%7}, {%8,%9}, {%0,%1,%2,%3};" \
        : "+f"((d)[0]), "+f"((d)[1]), "+f"((d)[2]), "+f"((d)[3]) \
        : "r"(a0), "r"(a1), "r"(a2), "r"(a3), "r"(b0), "r"(b1))
#define LDSM4(r0, r1, r2, r3, a) \
    asm volatile("ldmatrix.sync.aligned.m8n8.x4.shared.b16 {%0,%1,%2,%3},[%4];" \
        : "=r"(r0), "=r"(r1), "=r"(r2), "=r"(r3) : "r"(a))
#define LDSM4T(r0, r1, r2, r3, a) \
    asm volatile("ldmatrix.sync.aligned.m8n8.x4.trans.shared.b16 {%0,%1,%2,%3},[%4];" \
        : "=r"(r0), "=r"(r1), "=r"(r2), "=r"(r3) : "r"(a))
#define CP16(dst, src) \
    asm volatile("cp.async.cg.shared.global [%0], [%1], 16;" :: "r"(dst), "l"(src))
#define CPCOMMIT() asm volatile("cp.async.commit_group;")
#define CPWAITG(N) asm volatile("cp.async.wait_group %0;" :: "n"(N) : "memory")

__device__ __forceinline__ void split8(const float4 x, uint2& hi, uint2& lo) {
    __half h0 = __float2half_rn(x.x), h1 = __float2half_rn(x.y);
    __half h2 = __float2half_rn(x.z), h3 = __float2half_rn(x.w);
    __half e0 = __float2half_rn(x.x - __half2float(h0));
    __half e1 = __float2half_rn(x.y - __half2float(h1));
    __half e2 = __float2half_rn(x.z - __half2float(h2));
    __half e3 = __float2half_rn(x.w - __half2float(h3));
    __half2 a = __halves2half2(h0, h1), b = __halves2half2(h2, h3);
    __half2 c = __halves2half2(e0, e1), d = __halves2half2(e2, e3);
    hi.x = *(uint32_t*)&a; hi.y = *(uint32_t*)&b;
    lo.x = *(uint32_t*)&c; lo.y = *(uint32_t*)&d;
}

// attn smem (half-index offsets unless noted). Rows stride 72 halves.
// R13: K hi-only (2-pass S) -> K bufs halve.
#define SQH 0        // [64][72]
#define SQL 4608
#define SKB 9216     // 2 bufs x (KH 64x72) = 4608 halves each
#define SP  18432    // [64][72]
#define VBB 46080    // BYTE offset: V [256][64] halves, 128B rows, XOR-swizzled
#define FOFFB 78848  // BYTE offset of float region
#define RM 0
#define FF 128
#define LR 192
#define ATTN_SMEM (FOFFB + 320 * 4)   // 80,128 B -> 2 CTAs/SM

// ---------------------------------------------------------------------------
// conv bodies (validated R8-R12), unchanged.
// ---------------------------------------------------------------------------
__device__ __forceinline__
void conv_qk_body(__half* smc, float* sbias, const float* __restrict__ X,
                  const float* __restrict__ W, const float* __restrict__ bias,
                  __half* __restrict__ Y, int C, float scale, int b, int n0) {
    const int XL = 4352, WH = 8704, WL = 11264;
    const int tid = threadIdx.x, lane = tid & 31, w = tid >> 5;
    const int gid = lane >> 2, tig = lane & 3, lr = lane & 15, lc = (lane >> 4) << 3;
    const uint32_t sb = smem_u32(smc);
    if (tid < 64) sbias[tid] = bias[tid];
    float acc[8][4];
    #pragma unroll
    for (int i = 0; i < 8; i++)
        #pragma unroll
        for (int e = 0; e < 4; e++) acc[i][e] = 0.f;

    for (int c0 = 0; c0 < C; c0 += 32) {
        __syncthreads();
        #pragma unroll
        for (int p = 0; p < 4; p++) {
            int idx = tid + p * 256, cc = idx >> 5, n4 = (idx & 31) << 2;
            float4 x = *reinterpret_cast<const float4*>(X + ((size_t)b * C + c0 + cc) * NTOK + n0 + n4);
            uint2 hi, lo; split8(x, hi, lo);
            *reinterpret_cast<uint2*>(smc + cc * 136 + n4) = hi;
            *reinterpret_cast<uint2*>(smc + XL + cc * 136 + n4) = lo;
        }
        #pragma unroll
        for (int p = 0; p < 2; p++) {
            int idx = tid + p * 256, oo = idx >> 3, c4 = (idx & 7) << 2;
            float4 x = *reinterpret_cast<const float4*>(W + (size_t)oo * C + c0 + c4);
            uint2 hi, lo; split8(x, hi, lo);
            *reinterpret_cast<uint2*>(smc + WH + oo * 40 + c4) = hi;
            *reinterpret_cast<uint2*>(smc + WL + oo * 40 + c4) = lo;
        }
        __syncthreads();
        #pragma unroll
        for (int ks = 0; ks < 2; ks++) {
            uint32_t ah0, ah1, ah2, ah3, al0, al1, al2, al3;
            uint32_t ax = sb + 2u * (((ks << 4) + (lane & 7) + ((lane >> 4) << 3)) * 136
                                     + (w << 4) + (((lane >> 3) & 1) << 3));
            LDSM4T(ah0, ah1, ah2, ah3, ax);
            LDSM4T(al0, al1, al2, al3, ax + 2u * XL);
            #pragma unroll
            for (int p = 0; p < 4; p++) {
                uint32_t bh0, bh1, bh2, bh3, bl0, bl1, bl2, bl3;
                uint32_t aw = sb + 2u * (WH + ((p << 4) + lr) * 40 + (ks << 4) + lc);
                LDSM4(bh0, bh1, bh2, bh3, aw);
                LDSM4(bl0, bl1, bl2, bl3, aw + 2u * (WL - WH));
                MMA16(acc[2 * p],     ah0, ah1, ah2, ah3, bh0, bh2);
                MMA16(acc[2 * p + 1], ah0, ah1, ah2, ah3, bh1, bh3);
                MMA16(acc[2 * p],     ah0, ah1, ah2, ah3, bl0, bl2);
                MMA16(acc[2 * p + 1], ah0, ah1, ah2, ah3, bl1, bl3);
                MMA16(acc[2 * p],     al0, al1, al2, al3, bh0, bh2);
                MMA16(acc[2 * p + 1], al0, al1, al2, al3, bh1, bh3);
            }
        }
    }
    const int tok0 = n0 + (w << 4) + gid;
    #pragma unroll
    for (int nt = 0; nt < 8; nt++) {
        const int c = nt * 8 + 2 * tig;
        float b0s = sbias[c], b1s = sbias[c + 1];
        #pragma unroll
        for (int rr = 0; rr < 2; rr++) {
            float v0 = (acc[nt][2 * rr] + b0s) * scale;
            float v1 = (acc[nt][2 * rr + 1] + b1s) * scale;
            __half h0 = __float2half_rn(v0), h1 = __float2half_rn(v1);
            __half2 hh = __halves2half2(h0, h1);
            __half2 ll = __halves2half2(__float2half_rn(v0 - __half2float(h0)),
                                        __float2half_rn(v1 - __half2float(h1)));
            __half* yp = Y + ((size_t)b * NTOK + tok0 + rr * 8) * 128 + c;
            *(uint32_t*)yp = *(uint32_t*)&hh;
            *(uint32_t*)(yp + 64) = *(uint32_t*)&ll;
        }
    }
}

__device__ __forceinline__
void conv_v_body(__half* smc, float* sbias, const float* __restrict__ X,
                 const float* __restrict__ W, const float* __restrict__ bias,
                 __half* __restrict__ Y, int C, int b, int o0, int n0) {
    const int WHo = 4352;
    const int tid = threadIdx.x, lane = tid & 31, w = tid >> 5;
    const int gid = lane >> 2, tig = lane & 3, lr = lane & 15, lc = (lane >> 4) << 3;
    const uint32_t sb = smem_u32(smc);
    if (tid < 128) sbias[tid] = bias[o0 + tid];
    float acc[16][4];
    #pragma unroll
    for (int i = 0; i < 16; i++)
        #pragma unroll
        for (int e = 0; e < 4; e++) acc[i][e] = 0.f;

    for (int c0 = 0; c0 < C; c0 += 32) {
        __syncthreads();
        #pragma unroll
        for (int p = 0; p < 4; p++) {
            int idx = tid + p * 256, cc = idx >> 5, n4 = (idx & 31) << 2;
            float4 x = *reinterpret_cast<const float4*>(X + ((size_t)b * C + c0 + cc) * NTOK + n0 + n4);
            __half2 p0 = __floats2half2_rn(x.x, x.y), p1 = __floats2half2_rn(x.z, x.w);
            uint2 u; u.x = *(uint32_t*)&p0; u.y = *(uint32_t*)&p1;
            *reinterpret_cast<uint2*>(smc + cc * 136 + n4) = u;
        }
        #pragma unroll
        for (int p = 0; p < 4; p++) {
            int idx = tid + p * 256, oo = idx >> 3, c4 = (idx & 7) << 2;
            float4 x = *reinterpret_cast<const float4*>(W + (size_t)(o0 + oo) * C + c0 + c4);
            __half2 p0 = __floats2half2_rn(x.x, x.y), p1 = __floats2half2_rn(x.z, x.w);
            uint2 u; u.x = *(uint32_t*)&p0; u.y = *(uint32_t*)&p1;
            *reinterpret_cast<uint2*>(smc + WHo + oo * 40 + c4) = u;
        }
        __syncthreads();
        #pragma unroll
        for (int ks = 0; ks < 2; ks++) {
            uint32_t a0, a1, a2, a3;
            LDSM4(a0, a1, a2, a3, sb + 2u * (WHo + ((w << 4) + lr) * 40 + (ks << 4) + lc));
            #pragma unroll
            for (int tp = 0; tp < 8; tp++) {
                uint32_t v0, v1, v2, v3;
                uint32_t ax = sb + 2u * (((ks << 4) + (lane & 7) + ((lane >> 4) << 3)) * 136
                                         + (tp << 4) + (((lane >> 3) & 1) << 3));
                LDSM4T(v0, v1, v2, v3, ax);
                MMA16(acc[2 * tp],     a0, a1, a2, a3, v0, v2);
                MMA16(acc[2 * tp + 1], a0, a1, a2, a3, v1, v3);
            }
        }
    }
    const int orow = (w << 4) + gid;
    float br0 = sbias[orow], br1 = sbias[orow + 8];
    __half* vbo = Y + ((size_t)b * NT + (n0 >> 6)) * CVCH * 64;
    #pragma unroll
    for (int nt = 0; nt < 16; nt++) {
        int tokoff = nt * 8 + 2 * tig;
        int tadd = tokoff >> 6, j = tokoff & 63;
        __half2 h0 = __floats2half2_rn(acc[nt][0] + br0, acc[nt][1] + br0);
        __half2 h1 = __floats2half2_rn(acc[nt][2] + br1, acc[nt][3] + br1);
        __half* p0 = vbo + ((size_t)tadd * CVCH + o0 + orow) * 64 + j;
        *(uint32_t*)p0 = *(uint32_t*)&h0;
        *(uint32_t*)(p0 + 8 * 64) = *(uint32_t*)&h1;
    }
}

__global__ __launch_bounds__(256)
void fused_conv(const float* __restrict__ gate, const float* __restrict__ skip,
                const float* __restrict__ Wq, const float* __restrict__ bq,
                const float* __restrict__ Wk, const float* __restrict__ bk,
                const float* __restrict__ Wv, const float* __restrict__ bv,
                __half* __restrict__ q, __half* __restrict__ k,
                __half* __restrict__ v, float scale) {
    __shared__ __half smc[13824];
    __shared__ float sbias[128];
    const int gx = blockIdx.x, b = blockIdx.z;
    if (gx < 32) {
        conv_qk_body(smc, sbias, gate, Wq, bq, q, 512, scale, b, gx << 7);
    } else if (gx < 64) {
        conv_qk_body(smc, sbias, skip, Wk, bk, k, 256, 1.0f, b, (gx - 32) << 7);
    } else {
        const int vx = gx - 64;
        conv_v_body(smc, sbias, skip, Wv, bv, v, 256, b,
                    (vx >> 5) << 7, (vx & 31) << 7);
    }
}

// ---------------------------------------------------------------------------
// Flash attention. R13: 2-pass S (full q x fp16 k_hi); K hi-only buffers.
// ---------------------------------------------------------------------------
__global__ __launch_bounds__(256, 2)
void attn_kernel(const float* __restrict__ skip, const float* __restrict__ gamma,
                 float* __restrict__ out) {
    extern __shared__ __align__(16) char sm[];
    __half* smh = (__half*)sm;
    float* smf = (float*)(sm + FOFFB);
    const uint32_t sb = smem_u32(sm);
    const int tid = threadIdx.x, lane = tid & 31, w = tid >> 5;
    const int gid = lane >> 2, tig = lane & 3, lr = lane & 15, lc = (lane >> 4) << 3;
    const int r0 = (w & 3) << 4;
    const int ch = w >> 2;
    const int rq = (w & 1) << 5, cq = (w >> 1) << 6;
    const int b = blockIdx.y, i0 = blockIdx.x * TQ;
    const int row0 = r0 + gid, row1 = row0 + 8;

    const __half* qb = g_q16 + (size_t)b * NTOK * 128;
    const __half* kb = g_k16 + (size_t)b * NTOK * 128;
    const __half* vbg = g_v16 + (size_t)b * NT * CVCH * TK;

    // prologue: group1 = Q, group2 = K(0) hi only
    #pragma unroll
    for (int p = 0; p < 4; p++) {
        int chunk = tid + p * 256, row = chunk >> 4, c16 = chunk & 15;
        uint32_t d = sb + 2u * (c16 < 8 ? SQH + row * 72 + c16 * 8
                                        : SQL + row * 72 + (c16 - 8) * 8);
        CP16(d, qb + (size_t)(i0 + row) * 128 + c16 * 8);
    }
    CPCOMMIT();
    #pragma unroll
    for (int p = 0; p < 2; p++) {
        int chunk = tid + p * 256, row = chunk >> 3, c8 = chunk & 7;
        CP16(sb + 2u * (SKB + row * 72 + c8 * 8), kb + (size_t)row * 128 + c8 * 8);
    }
    CPCOMMIT();

    float oacc[16][4];
    #pragma unroll
    for (int t = 0; t < 16; t++)
        #pragma unroll
        for (int e = 0; e < 4; e++) oacc[t][e] = 0.f;
    float rm0 = -1e30f, rm1 = -1e30f, lsum0 = 0.f, lsum1 = 0.f;

    for (int t = 0; t < NT; t++) {
        const int buf = t & 1;
        __syncthreads();   // PV(t-1) complete: vbuf + kbuf[(t+1)&1] free
        // issue V(t) (group), then K(t+1) hi (group)
        {
            const __half* vt = vbg + (size_t)t * CVCH * TK;
            #pragma unroll
            for (int p = 0; p < 8; p++) {
                int chunk = tid + p * 256, row = chunk >> 3, cb = chunk & 7;
                uint32_t d = sb + VBB + row * 128 + (((uint32_t)(cb ^ (row & 7))) << 4);
                CP16(d, vt + (size_t)row * 64 + cb * 8);
            }
            CPCOMMIT();
            const int tn = (t + 1) & (NT - 1);
            const int kbase = SKB + ((t + 1) & 1) * 4608;
            #pragma unroll
            for (int p = 0; p < 2; p++) {
                int chunk = tid + p * 256, row = chunk >> 3, c8 = chunk & 7;
                CP16(sb + 2u * (kbase + row * 72 + c8 * 8),
                     kb + (size_t)(tn * TK + row) * 128 + c8 * 8);
            }
            CPCOMMIT();
        }
        CPWAITG(2);        // K(t) (and Q) ready; V(t), K(t+1) may pend
        __syncthreads();

        // S = (qh+ql).kh (2-pass), 4 independent acc chains
        const int kh = SKB + buf * 4608;
        float sacc[4][4];
        #pragma unroll
        for (int tt = 0; tt < 4; tt++)
            #pragma unroll
            for (int e = 0; e < 4; e++) sacc[tt][e] = 0.f;
        #pragma unroll
        for (int kk = 0; kk < 4; kk++) {
            uint32_t ah0, ah1, ah2, ah3, al0, al1, al2, al3;
            uint32_t aq = sb + 2u * (SQH + (r0 + lr) * 72 + kk * 16 + lc);
            LDSM4(ah0, ah1, ah2, ah3, aq);
            LDSM4(al0, al1, al2, al3, aq + 2u * SQL);
            uint32_t bh[2][4];
            #pragma unroll
            for (int tp = 0; tp < 2; tp++) {
                uint32_t ak = sb + 2u * (kh + (ch * 32 + tp * 16 + lr) * 72 + kk * 16 + lc);
                LDSM4(bh[tp][0], bh[tp][1], bh[tp][2], bh[tp][3], ak);
            }
            MMA16(sacc[0], ah0, ah1, ah2, ah3, bh[0][0], bh[0][2]);
            MMA16(sacc[1], ah0, ah1, ah2, ah3, bh[0][1], bh[0][3]);
            MMA16(sacc[2], ah0, ah1, ah2, ah3, bh[1][0], bh[1][2]);
            MMA16(sacc[3], ah0, ah1, ah2, ah3, bh[1][1], bh[1][3]);
            MMA16(sacc[0], al0, al1, al2, al3, bh[0][0], bh[0][2]);
            MMA16(sacc[1], al0, al1, al2, al3, bh[0][1], bh[0][3]);
            MMA16(sacc[2], al0, al1, al2, al3, bh[1][0], bh[1][2]);
            MMA16(sacc[3], al0, al1, al2, al3, bh[1][1], bh[1][3]);
        }
        float mx0 = -1e30f, mx1 = -1e30f;
        #pragma unroll
        for (int tt = 0; tt < 4; tt++) {
            mx0 = fmaxf(mx0, fmaxf(sacc[tt][0], sacc[tt][1]));
            mx1 = fmaxf(mx1, fmaxf(sacc[tt][2], sacc[tt][3]));
        }
        mx0 = fmaxf(mx0, __shfl_xor_sync(0xFFFFFFFFu, mx0, 1));
        mx0 = fmaxf(mx0, __shfl_xor_sync(0xFFFFFFFFu, mx0, 2));
        mx1 = fmaxf(mx1, __shfl_xor_sync(0xFFFFFFFFu, mx1, 1));
        mx1 = fmaxf(mx1, __shfl_xor_sync(0xFFFFFFFFu, mx1, 2));
        if (tig == 0) {
            smf[RM + row0 * 2 + ch] = mx0;
            smf[RM + row1 * 2 + ch] = mx1;
        }
        __syncthreads();

        // online softmax -> P fp16
        float mn0 = fmaxf(rm0, fmaxf(smf[RM + row0 * 2], smf[RM + row0 * 2 + 1]));
        float mn1 = fmaxf(rm1, fmaxf(smf[RM + row1 * 2], smf[RM + row1 * 2 + 1]));
        float f0 = fast_exp2(rm0 - mn0), f1 = fast_exp2(rm1 - mn1);
        rm0 = mn0; rm1 = mn1;
        if (tig == 0 && ch == 0) { smf[FF + row0] = f0; smf[FF + row1] = f1; }
        float ps0 = 0.f, ps1 = 0.f;
        #pragma unroll
        for (int tt = 0; tt < 4; tt++) {
            float p00 = fast_exp2(sacc[tt][0] - mn0);
            float p01 = fast_exp2(sacc[tt][1] - mn0);
            float p10 = fast_exp2(sacc[tt][2] - mn1);
            float p11 = fast_exp2(sacc[tt][3] - mn1);
            ps0 += p00 + p01; ps1 += p10 + p11;
            __half2 h0 = __floats2half2_rn(p00, p01);
            __half2 h1 = __floats2half2_rn(p10, p11);
            const int cc = ch * 32 + tt * 8 + 2 * tig;
            *(uint32_t*)(smh + SP + row0 * 72 + cc) = *(uint32_t*)&h0;
            *(uint32_t*)(smh + SP + row1 * 72 + cc) = *(uint32_t*)&h1;
        }
        lsum0 = lsum0 * f0 + ps0;
        lsum1 = lsum1 * f1 + ps1;
        CPWAITG(1);        // V(t) ready; K(t+1) may pend
        __syncthreads();   // P + V visible

        // rescale O (skipped when no row max changed), then O += P.V^T
        float fa0 = smf[FF + rq + gid], fa1 = smf[FF + rq + gid + 8];
        float fb0 = smf[FF + rq + 16 + gid], fb1 = smf[FF + rq + 16 + gid + 8];
        if (!__all_sync(0xFFFFFFFFu,
                        (fa0 == 1.f) & (fa1 == 1.f) & (fb0 == 1.f) & (fb1 == 1.f))) {
            #pragma unroll
            for (int nt = 0; nt < 8; nt++) {
                oacc[nt][0] *= fa0; oacc[nt][1] *= fa0;
                oacc[nt][2] *= fa1; oacc[nt][3] *= fa1;
                oacc[8 + nt][0] *= fb0; oacc[8 + nt][1] *= fb0;
                oacc[8 + nt][2] *= fb1; oacc[8 + nt][3] *= fb1;
            }
        }
        #pragma unroll
        for (int kk = 0; kk < 4; kk++) {
            uint32_t pa0, pa1, pa2, pa3, qa0, qa1, qa2, qa3;
            uint32_t ap = sb + 2u * (SP + (rq + lr) * 72 + kk * 16 + lc);
            LDSM4(pa0, pa1, pa2, pa3, ap);
            LDSM4(qa0, qa1, qa2, qa3, ap + 2u * (16 * 72));
            const uint32_t cb = (uint32_t)(kk * 2 + (lc >> 3));
            #pragma unroll
            for (int np = 0; np < 4; np++) {
                const int vrow = cq + np * 16 + lr;
                uint32_t va = sb + VBB + vrow * 128 + ((cb ^ (uint32_t)(vrow & 7)) << 4);
                uint32_t v0, v1, v2, v3;
                LDSM4(v0, v1, v2, v3, va);
                MMA16(oacc[2 * np],         pa0, pa1, pa2, pa3, v0, v2);
                MMA16(oacc[2 * np + 1],     pa0, pa1, pa2, pa3, v1, v3);
                MMA16(oacc[8 + 2 * np],     qa0, qa1, qa2, qa3, v0, v2);
                MMA16(oacc[8 + 2 * np + 1], qa0, qa1, qa2, qa3, v1, v3);
            }
        }
    }

    // final l reduction + epilogue
    lsum0 += __shfl_xor_sync(0xFFFFFFFFu, lsum0, 1);
    lsum0 += __shfl_xor_sync(0xFFFFFFFFu, lsum0, 2);
    lsum1 += __shfl_xor_sync(0xFFFFFFFFu, lsum1, 1);
    lsum1 += __shfl_xor_sync(0xFFFFFFFFu, lsum1, 2);
    __syncthreads();
    if (tig == 0) {
        smf[LR + row0 * 2 + ch] = lsum0;
        smf[LR + row1 * 2 + ch] = lsum1;
    }
    __syncthreads();

    const float gm = __ldg(gamma);
    const float* skb = skip + (size_t)b * CVCH * NTOK;
    float* ob = out + (size_t)b * CVCH * NTOK;
    #pragma unroll
    for (int mt = 0; mt < 2; mt++) {
        const int ra = rq + mt * 16 + gid, rb = ra + 8;
        const float fca = gm / (smf[LR + ra * 2] + smf[LR + ra * 2 + 1]);
        const float fcb = gm / (smf[LR + rb * 2] + smf[LR + rb * 2 + 1]);
        const int ia = i0 + ra, ib = i0 + rb;
        #pragma unroll
        for (int nt = 0; nt < 8; nt++) {
            const int c = cq + nt * 8 + 2 * tig;
            const size_t oA = (size_t)c * NTOK, oB = (size_t)(c + 1) * NTOK;
            const float* acc = oacc[mt * 8 + nt];
            ob[oA + ia] = acc[0] * fca + skb[oA + ia];
            ob[oB + ia] = acc[1] * fca + skb[oB + ia];
            ob[oA + ib] = acc[2] * fcb + skb[oA + ib];
            ob[oB + ib] = acc[3] * fcb + skb[oB + ib];
        }
    }
}

// ---------------------------------------------------------------------------
static __half* s_q = nullptr;
static __half* s_k = nullptr;
static __half* s_v = nullptr;

extern "C" void kernel_launch(void* const* d_in, const int* in_sizes, int n_in,
                              void* d_out, int out_size) {
    (void)in_sizes; (void)n_in; (void)out_size;
    static bool initialized = []() {
        void* p;
        cudaGetSymbolAddress(&p, g_q16); s_q = (__half*)p;
        cudaGetSymbolAddress(&p, g_k16); s_k = (__half*)p;
        cudaGetSymbolAddress(&p, g_v16); s_v = (__half*)p;
        cudaFuncSetAttribute(attn_kernel, cudaFuncAttributeMaxDynamicSharedMemorySize,
                             ATTN_SMEM);
        return true;
    }();
    (void)initialized;

    const float* gate  = (const float*)d_in[0];
    const float* skip  = (const float*)d_in[1];
    const float* Wq    = (const float*)d_in[2];
    const float* bq    = (const float*)d_in[3];
    const float* Wk    = (const float*)d_in[4];
    const float* bk    = (const float*)d_in[5];
    const float* Wv    = (const float*)d_in[6];
    const float* bv    = (const float*)d_in[7];
    const float* gamma = (const float*)d_in[8];
    float* out = (float*)d_out;

    const float LOG2E = 1.4426950408889634f;

    fused_conv<<<dim3(128, 1, NB), 256>>>(gate, skip, Wq, bq, Wk, bk, Wv, bv,
                                          s_q, s_k, s_v, LOG2E);
    attn_kernel<<<dim3(NTOK / TQ, NB), 256, ATTN_SMEM>>>(skip, gamma, out);
}

// round 15
// speedup vs baseline: 1.3765x; 1.0904x over previous
#include <cuda_runtime.h>
#include <cuda_fp16.h>
#include <cstdint>
#include <cstddef>

#define NTOK 4096
#define DQK  64
#define CVCH 256
#define NB   4
#define TQ   64
#define TK   64
#define NT   (NTOK / TK)   // 64

__device__ __align__(16) __half g_q16[NB * NTOK * 128];     // [b][n][hi64|pad]
__device__ __align__(16) __half g_k16[NB * NTOK * 128];
__device__ __align__(16) __half g_v16[NB * NT * CVCH * TK]; // [b][t][c][64j]

__device__ __forceinline__ float fast_exp2(float x) {
    float r; asm("ex2.approx.ftz.f32 %0, %1;" : "=f"(r) : "f"(x)); return r;
}
__device__ __forceinline__ uint32_t smem_u32(const void* p) {
    uint32_t a;
    asm("{ .reg .u64 t; cvta.to.shared.u64 t, %1; cvt.u32.u64 %0, t; }" : "=r"(a) : "l"(p));
    return a;
}
#define MMA16(d, a0, a1, a2, a3, b0, b1) \
    asm volatile("mma.sync.aligned.m16n8k16.row.col.f32.f16.f16.f32 " \
        "{%0,%1,%2,%3}, {%4,%5,%6,%7}, {%8,%9}, {%0,%1,%2,%3};" \
        : "+f"((d)[0]), "+f"((d)[1]), "+f"((d)[2]), "+f"((d)[3]) \
        : "r"(a0), "r"(a1), "r"(a2), "r"(a3), "r"(b0), "r"(b1))
#define LDSM4(r0, r1, r2, r3, a) \
    asm volatile("ldmatrix.sync.aligned.m8n8.x4.shared.b16 {%0,%1,%2,%3},[%4];" \
        : "=r"(r0), "=r"(r1), "=r"(r2), "=r"(r3) : "r"(a))
#define LDSM4T(r0, r1, r2, r3, a) \
    asm volatile("ldmatrix.sync.aligned.m8n8.x4.trans.shared.b16 {%0,%1,%2,%3},[%4];" \
        : "=r"(r0), "=r"(r1), "=r"(r2), "=r"(r3) : "r"(a))
#define CP16(dst, src) \
    asm volatile("cp.async.cg.shared.global [%0], [%1], 16;" :: "r"(dst), "l"(src))
#define CPCOMMIT() asm volatile("cp.async.commit_group;")
#define CPWAITG(N) asm volatile("cp.async.wait_group %0;" :: "n"(N) : "memory")

__device__ __forceinline__ void split8(const float4 x, uint2& hi, uint2& lo) {
    __half h0 = __float2half_rn(x.x), h1 = __float2half_rn(x.y);
    __half h2 = __float2half_rn(x.z), h3 = __float2half_rn(x.w);
    __half e0 = __float2half_rn(x.x - __half2float(h0));
    __half e1 = __float2half_rn(x.y - __half2float(h1));
    __half e2 = __float2half_rn(x.z - __half2float(h2));
    __half e3 = __float2half_rn(x.w - __half2float(h3));
    __half2 a = __halves2half2(h0, h1), b = __halves2half2(h2, h3);
    __half2 c = __halves2half2(e0, e1), d = __halves2half2(e2, e3);
    hi.x = *(uint32_t*)&a; hi.y = *(uint32_t*)&b;
    lo.x = *(uint32_t*)&c; lo.y = *(uint32_t*)&d;
}

// attn smem (half-index offsets unless noted). Rows stride 72 halves.
// Q hi-only AND K hi-only (single-pass S).
#define SQH 0        // [64][72]
#define SKB 4608     // 2 bufs x (KH 64x72) = 4608 halves each
#define SP  13824    // [64][72]
#define VBB 36864    // BYTE offset: V [256][64] halves, 128B rows, XOR-swizzled
#define FOFFB 69632  // BYTE offset of float region
#define RM 0
#define FF 128
#define LR 192
#define ATTN_SMEM (FOFFB + 320 * 4)   // 70,912 B -> 2 CTAs/SM (reg-bound)

// ---------------------------------------------------------------------------
// conv q/k: fp16 GEMM, 3-pass accumulate (fp32-accurate), hi-only output.
// ---------------------------------------------------------------------------
__device__ __forceinline__
void conv_qk_body(__half* smc, float* sbias, const float* __restrict__ X,
                  const float* __restrict__ W, const float* __restrict__ bias,
                  __half* __restrict__ Y, int C, float scale, int b, int n0) {
    const int XL = 4352, WH = 8704, WL = 11264;
    const int tid = threadIdx.x, lane = tid & 31, w = tid >> 5;
    const int gid = lane >> 2, tig = lane & 3, lr = lane & 15, lc = (lane >> 4) << 3;
    const uint32_t sb = smem_u32(smc);
    if (tid < 64) sbias[tid] = bias[tid];
    float acc[8][4];
    #pragma unroll
    for (int i = 0; i < 8; i++)
        #pragma unroll
        for (int e = 0; e < 4; e++) acc[i][e] = 0.f;

    for (int c0 = 0; c0 < C; c0 += 32) {
        __syncthreads();
        #pragma unroll
        for (int p = 0; p < 4; p++) {
            int idx = tid + p * 256, cc = idx >> 5, n4 = (idx & 31) << 2;
            float4 x = *reinterpret_cast<const float4*>(X + ((size_t)b * C + c0 + cc) * NTOK + n0 + n4);
            uint2 hi, lo; split8(x, hi, lo);
            *reinterpret_cast<uint2*>(smc + cc * 136 + n4) = hi;
            *reinterpret_cast<uint2*>(smc + XL + cc * 136 + n4) = lo;
        }
        #pragma unroll
        for (int p = 0; p < 2; p++) {
            int idx = tid + p * 256, oo = idx >> 3, c4 = (idx & 7) << 2;
            float4 x = *reinterpret_cast<const float4*>(W + (size_t)oo * C + c0 + c4);
            uint2 hi, lo; split8(x, hi, lo);
            *reinterpret_cast<uint2*>(smc + WH + oo * 40 + c4) = hi;
            *reinterpret_cast<uint2*>(smc + WL + oo * 40 + c4) = lo;
        }
        __syncthreads();
        #pragma unroll
        for (int ks = 0; ks < 2; ks++) {
            uint32_t ah0, ah1, ah2, ah3, al0, al1, al2, al3;
            uint32_t ax = sb + 2u * (((ks << 4) + (lane & 7) + ((lane >> 4) << 3)) * 136
                                     + (w << 4) + (((lane >> 3) & 1) << 3));
            LDSM4T(ah0, ah1, ah2, ah3, ax);
            LDSM4T(al0, al1, al2, al3, ax + 2u * XL);
            #pragma unroll
            for (int p = 0; p < 4; p++) {
                uint32_t bh0, bh1, bh2, bh3, bl0, bl1, bl2, bl3;
                uint32_t aw = sb + 2u * (WH + ((p << 4) + lr) * 40 + (ks << 4) + lc);
                LDSM4(bh0, bh1, bh2, bh3, aw);
                LDSM4(bl0, bl1, bl2, bl3, aw + 2u * (WL - WH));
                MMA16(acc[2 * p],     ah0, ah1, ah2, ah3, bh0, bh2);
                MMA16(acc[2 * p + 1], ah0, ah1, ah2, ah3, bh1, bh3);
                MMA16(acc[2 * p],     ah0, ah1, ah2, ah3, bl0, bl2);
                MMA16(acc[2 * p + 1], ah0, ah1, ah2, ah3, bl1, bl3);
                MMA16(acc[2 * p],     al0, al1, al2, al3, bh0, bh2);
                MMA16(acc[2 * p + 1], al0, al1, al2, al3, bh1, bh3);
            }
        }
    }
    const int tok0 = n0 + (w << 4) + gid;
    #pragma unroll
    for (int nt = 0; nt < 8; nt++) {
        const int c = nt * 8 + 2 * tig;
        float b0s = sbias[c], b1s = sbias[c + 1];
        #pragma unroll
        for (int rr = 0; rr < 2; rr++) {
            float v0 = (acc[nt][2 * rr] + b0s) * scale;
            float v1 = (acc[nt][2 * rr + 1] + b1s) * scale;
            __half2 hh = __floats2half2_rn(v0, v1);
            __half* yp = Y + ((size_t)b * NTOK + tok0 + rr * 8) * 128 + c;
            *(uint32_t*)yp = *(uint32_t*)&hh;
        }
    }
}

__device__ __forceinline__
void conv_v_body(__half* smc, float* sbias, const float* __restrict__ X,
                 const float* __restrict__ W, const float* __restrict__ bias,
                 __half* __restrict__ Y, int C, int b, int o0, int n0) {
    const int WHo = 4352;
    const int tid = threadIdx.x, lane = tid & 31, w = tid >> 5;
    const int gid = lane >> 2, tig = lane & 3, lr = lane & 15, lc = (lane >> 4) << 3;
    const uint32_t sb = smem_u32(smc);
    if (tid < 128) sbias[tid] = bias[o0 + tid];
    float acc[16][4];
    #pragma unroll
    for (int i = 0; i < 16; i++)
        #pragma unroll
        for (int e = 0; e < 4; e++) acc[i][e] = 0.f;

    for (int c0 = 0; c0 < C; c0 += 32) {
        __syncthreads();
        #pragma unroll
        for (int p = 0; p < 4; p++) {
            int idx = tid + p * 256, cc = idx >> 5, n4 = (idx & 31) << 2;
            float4 x = *reinterpret_cast<const float4*>(X + ((size_t)b * C + c0 + cc) * NTOK + n0 + n4);
            __half2 p0 = __floats2half2_rn(x.x, x.y), p1 = __floats2half2_rn(x.z, x.w);
            uint2 u; u.x = *(uint32_t*)&p0; u.y = *(uint32_t*)&p1;
            *reinterpret_cast<uint2*>(smc + cc * 136 + n4) = u;
        }
        #pragma unroll
        for (int p = 0; p < 4; p++) {
            int idx = tid + p * 256, oo = idx >> 3, c4 = (idx & 7) << 2;
            float4 x = *reinterpret_cast<const float4*>(W + (size_t)(o0 + oo) * C + c0 + c4);
            __half2 p0 = __floats2half2_rn(x.x, x.y), p1 = __floats2half2_rn(x.z, x.w);
            uint2 u; u.x = *(uint32_t*)&p0; u.y = *(uint32_t*)&p1;
            *reinterpret_cast<uint2*>(smc + WHo + oo * 40 + c4) = u;
        }
        __syncthreads();
        #pragma unroll
        for (int ks = 0; ks < 2; ks++) {
            uint32_t a0, a1, a2, a3;
            LDSM4(a0, a1, a2, a3, sb + 2u * (WHo + ((w << 4) + lr) * 40 + (ks << 4) + lc));
            #pragma unroll
            for (int tp = 0; tp < 8; tp++) {
                uint32_t v0, v1, v2, v3;
                uint32_t ax = sb + 2u * (((ks << 4) + (lane & 7) + ((lane >> 4) << 3)) * 136
                                         + (tp << 4) + (((lane >> 3) & 1) << 3));
                LDSM4T(v0, v1, v2, v3, ax);
                MMA16(acc[2 * tp],     a0, a1, a2, a3, v0, v2);
                MMA16(acc[2 * tp + 1], a0, a1, a2, a3, v1, v3);
            }
        }
    }
    const int orow = (w << 4) + gid;
    float br0 = sbias[orow], br1 = sbias[orow + 8];
    __half* vbo = Y + ((size_t)b * NT + (n0 >> 6)) * CVCH * 64;
    #pragma unroll
    for (int nt = 0; nt < 16; nt++) {
        int tokoff = nt * 8 + 2 * tig;
        int tadd = tokoff >> 6, j = tokoff & 63;
        __half2 h0 = __floats2half2_rn(acc[nt][0] + br0, acc[nt][1] + br0);
        __half2 h1 = __floats2half2_rn(acc[nt][2] + br1, acc[nt][3] + br1);
        __half* p0 = vbo + ((size_t)tadd * CVCH + o0 + orow) * 64 + j;
        *(uint32_t*)p0 = *(uint32_t*)&h0;
        *(uint32_t*)(p0 + 8 * 64) = *(uint32_t*)&h1;
    }
}

__global__ __launch_bounds__(256)
void fused_conv(const float* __restrict__ gate, const float* __restrict__ skip,
                const float* __restrict__ Wq, const float* __restrict__ bq,
                const float* __restrict__ Wk, const float* __restrict__ bk,
                const float* __restrict__ Wv, const float* __restrict__ bv,
                __half* __restrict__ q, __half* __restrict__ k,
                __half* __restrict__ v, float scale) {
    __shared__ __half smc[13824];
    __shared__ float sbias[128];
    const int gx = blockIdx.x, b = blockIdx.z;
    if (gx < 32) {
        conv_qk_body(smc, sbias, gate, Wq, bq, q, 512, scale, b, gx << 7);
    } else if (gx < 64) {
        conv_qk_body(smc, sbias, skip, Wk, bk, k, 256, 1.0f, b, (gx - 32) << 7);
    } else {
        const int vx = gx - 64;
        conv_v_body(smc, sbias, skip, Wv, bv, v, 256, b,
                    (vx >> 5) << 7, (vx & 31) << 7);
    }
}

// ---------------------------------------------------------------------------
// Flash attention: single-pass fp16 S (q_hi x k_hi).
// ---------------------------------------------------------------------------
__global__ __launch_bounds__(256, 2)
void attn_kernel(const float* __restrict__ skip, const float* __restrict__ gamma,
                 float* __restrict__ out) {
    extern __shared__ __align__(16) char sm[];
    __half* smh = (__half*)sm;
    float* smf = (float*)(sm + FOFFB);
    const uint32_t sb = smem_u32(sm);
    const int tid = threadIdx.x, lane = tid & 31, w = tid >> 5;
    const int gid = lane >> 2, tig = lane & 3, lr = lane & 15, lc = (lane >> 4) << 3;
    const int r0 = (w & 3) << 4;
    const int ch = w >> 2;
    const int rq = (w & 1) << 5, cq = (w >> 1) << 6;
    const int b = blockIdx.y, i0 = blockIdx.x * TQ;
    const int row0 = r0 + gid, row1 = row0 + 8;

    const __half* qb = g_q16 + (size_t)b * NTOK * 128;
    const __half* kb = g_k16 + (size_t)b * NTOK * 128;
    const __half* vbg = g_v16 + (size_t)b * NT * CVCH * TK;

    // prologue: group1 = Q hi, group2 = K(0) hi
    #pragma unroll
    for (int p = 0; p < 2; p++) {
        int chunk = tid + p * 256, row = chunk >> 3, c8 = chunk & 7;
        CP16(sb + 2u * (SQH + row * 72 + c8 * 8), qb + (size_t)(i0 + row) * 128 + c8 * 8);
    }
    CPCOMMIT();
    #pragma unroll
    for (int p = 0; p < 2; p++) {
        int chunk = tid + p * 256, row = chunk >> 3, c8 = chunk & 7;
        CP16(sb + 2u * (SKB + row * 72 + c8 * 8), kb + (size_t)row * 128 + c8 * 8);
    }
    CPCOMMIT();

    float oacc[16][4];
    #pragma unroll
    for (int t = 0; t < 16; t++)
        #pragma unroll
        for (int e = 0; e < 4; e++) oacc[t][e] = 0.f;
    float rm0 = -1e30f, rm1 = -1e30f, lsum0 = 0.f, lsum1 = 0.f;

    for (int t = 0; t < NT; t++) {
        const int buf = t & 1;
        __syncthreads();   // PV(t-1) complete: vbuf + kbuf[(t+1)&1] free
        // issue V(t) (group), then K(t+1) hi (group)
        {
            const __half* vt = vbg + (size_t)t * CVCH * TK;
            #pragma unroll
            for (int p = 0; p < 8; p++) {
                int chunk = tid + p * 256, row = chunk >> 3, cb = chunk & 7;
                uint32_t d = sb + VBB + row * 128 + (((uint32_t)(cb ^ (row & 7))) << 4);
                CP16(d, vt + (size_t)row * 64 + cb * 8);
            }
            CPCOMMIT();
            const int tn = (t + 1) & (NT - 1);
            const int kbase = SKB + ((t + 1) & 1) * 4608;
            #pragma unroll
            for (int p = 0; p < 2; p++) {
                int chunk = tid + p * 256, row = chunk >> 3, c8 = chunk & 7;
                CP16(sb + 2u * (kbase + row * 72 + c8 * 8),
                     kb + (size_t)(tn * TK + row) * 128 + c8 * 8);
            }
            CPCOMMIT();
        }
        CPWAITG(2);        // K(t) (and Q) ready; V(t), K(t+1) may pend
        __syncthreads();

        // S = qh.kh (single pass), 4 independent acc chains
        const int kh = SKB + buf * 4608;
        float sacc[4][4];
        #pragma unroll
        for (int tt = 0; tt < 4; tt++)
            #pragma unroll
            for (int e = 0; e < 4; e++) sacc[tt][e] = 0.f;
        #pragma unroll
        for (int kk = 0; kk < 4; kk++) {
            uint32_t ah0, ah1, ah2, ah3;
            uint32_t aq = sb + 2u * (SQH + (r0 + lr) * 72 + kk * 16 + lc);
            LDSM4(ah0, ah1, ah2, ah3, aq);
            uint32_t bh[2][4];
            #pragma unroll
            for (int tp = 0; tp < 2; tp++) {
                uint32_t ak = sb + 2u * (kh + (ch * 32 + tp * 16 + lr) * 72 + kk * 16 + lc);
                LDSM4(bh[tp][0], bh[tp][1], bh[tp][2], bh[tp][3], ak);
            }
            MMA16(sacc[0], ah0, ah1, ah2, ah3, bh[0][0], bh[0][2]);
            MMA16(sacc[1], ah0, ah1, ah2, ah3, bh[0][1], bh[0][3]);
            MMA16(sacc[2], ah0, ah1, ah2, ah3, bh[1][0], bh[1][2]);
            MMA16(sacc[3], ah0, ah1, ah2, ah3, bh[1][1], bh[1][3]);
        }
        float mx0 = -1e30f, mx1 = -1e30f;
        #pragma unroll
        for (int tt = 0; tt < 4; tt++) {
            mx0 = fmaxf(mx0, fmaxf(sacc[tt][0], sacc[tt][1]));
            mx1 = fmaxf(mx1, fmaxf(sacc[tt][2], sacc[tt][3]));
        }
        mx0 = fmaxf(mx0, __shfl_xor_sync(0xFFFFFFFFu, mx0, 1));
        mx0 = fmaxf(mx0, __shfl_xor_sync(0xFFFFFFFFu, mx0, 2));
        mx1 = fmaxf(mx1, __shfl_xor_sync(0xFFFFFFFFu, mx1, 1));
        mx1 = fmaxf(mx1, __shfl_xor_sync(0xFFFFFFFFu, mx1, 2));
        if (tig == 0) {
            smf[RM + row0 * 2 + ch] = mx0;
            smf[RM + row1 * 2 + ch] = mx1;
        }
        __syncthreads();

        // online softmax -> P fp16
        float mn0 = fmaxf(rm0, fmaxf(smf[RM + row0 * 2], smf[RM + row0 * 2 + 1]));
        float mn1 = fmaxf(rm1, fmaxf(smf[RM + row1 * 2], smf[RM + row1 * 2 + 1]));
        float f0 = fast_exp2(rm0 - mn0), f1 = fast_exp2(rm1 - mn1);
        rm0 = mn0; rm1 = mn1;
        if (tig == 0 && ch == 0) { smf[FF + row0] = f0; smf[FF + row1] = f1; }
        float ps0 = 0.f, ps1 = 0.f;
        #pragma unroll
        for (int tt = 0; tt < 4; tt++) {
            float p00 = fast_exp2(sacc[tt][0] - mn0);
            float p01 = fast_exp2(sacc[tt][1] - mn0);
            float p10 = fast_exp2(sacc[tt][2] - mn1);
            float p11 = fast_exp2(sacc[tt][3] - mn1);
            ps0 += p00 + p01; ps1 += p10 + p11;
            __half2 h0 = __floats2half2_rn(p00, p01);
            __half2 h1 = __floats2half2_rn(p10, p11);
            const int cc = ch * 32 + tt * 8 + 2 * tig;
            *(uint32_t*)(smh + SP + row0 * 72 + cc) = *(uint32_t*)&h0;
            *(uint32_t*)(smh + SP + row1 * 72 + cc) = *(uint32_t*)&h1;
        }
        lsum0 = lsum0 * f0 + ps0;
        lsum1 = lsum1 * f1 + ps1;
        CPWAITG(1);        // V(t) ready; K(t+1) may pend
        __syncthreads();   // P + V visible

        // rescale O (skipped when no row max changed), then O += P.V^T
        float fa0 = smf[FF + rq + gid], fa1 = smf[FF + rq + gid + 8];
        float fb0 = smf[FF + rq + 16 + gid], fb1 = smf[FF + rq + 16 + gid + 8];
        if (!__all_sync(0xFFFFFFFFu,
                        (fa0 == 1.f) & (fa1 == 1.f) & (fb0 == 1.f) & (fb1 == 1.f))) {
            #pragma unroll
            for (int nt = 0; nt < 8; nt++) {
                oacc[nt][0] *= fa0; oacc[nt][1] *= fa0;
                oacc[nt][2] *= fa1; oacc[nt][3] *= fa1;
                oacc[8 + nt][0] *= fb0; oacc[8 + nt][1] *= fb0;
                oacc[8 + nt][2] *= fb1; oacc[8 + nt][3] *= fb1;
            }
        }
        #pragma unroll
        for (int kk = 0; kk < 4; kk++) {
            uint32_t pa0, pa1, pa2, pa3, qa0, qa1, qa2, qa3;
            uint32_t ap = sb + 2u * (SP + (rq + lr) * 72 + kk * 16 + lc);
            LDSM4(pa0, pa1, pa2, pa3, ap);
            LDSM4(qa0, qa1, qa2, qa3, ap + 2u * (16 * 72));
            const uint32_t cb = (uint32_t)(kk * 2 + (lc >> 3));
            #pragma unroll
            for (int np = 0; np < 4; np++) {
                const int vrow = cq + np * 16 + lr;
                uint32_t va = sb + VBB + vrow * 128 + ((cb ^ (uint32_t)(vrow & 7)) << 4);
                uint32_t v0, v1, v2, v3;
                LDSM4(v0, v1, v2, v3, va);
                MMA16(oacc[2 * np],         pa0, pa1, pa2, pa3, v0, v2);
                MMA16(oacc[2 * np + 1],     pa0, pa1, pa2, pa3, v1, v3);
                MMA16(oacc[8 + 2 * np],     qa0, qa1, qa2, qa3, v0, v2);
                MMA16(oacc[8 + 2 * np + 1], qa0, qa1, qa2, qa3, v1, v3);
            }
        }
    }

    // final l reduction + epilogue
    lsum0 += __shfl_xor_sync(0xFFFFFFFFu, lsum0, 1);
    lsum0 += __shfl_xor_sync(0xFFFFFFFFu, lsum0, 2);
    lsum1 += __shfl_xor_sync(0xFFFFFFFFu, lsum1, 1);
    lsum1 += __shfl_xor_sync(0xFFFFFFFFu, lsum1, 2);
    __syncthreads();
    if (tig == 0) {
        smf[LR + row0 * 2 + ch] = lsum0;
        smf[LR + row1 * 2 + ch] = lsum1;
    }
    __syncthreads();

    const float gm = __ldg(gamma);
    const float* skb = skip + (size_t)b * CVCH * NTOK;
    float* ob = out + (size_t)b * CVCH * NTOK;
    #pragma unroll
    for (int mt = 0; mt < 2; mt++) {
        const int ra = rq + mt * 16 + gid, rb = ra + 8;
        const float fca = gm / (smf[LR + ra * 2] + smf[LR + ra * 2 + 1]);
        const float fcb = gm / (smf[LR + rb * 2] + smf[LR + rb * 2 + 1]);
        const int ia = i0 + ra, ib = i0 + rb;
        #pragma unroll
        for (int nt = 0; nt < 8; nt++) {
            const int c = cq + nt * 8 + 2 * tig;
            const size_t oA = (size_t)c * NTOK, oB = (size_t)(c + 1) * NTOK;
            const float* acc = oacc[mt * 8 + nt];
            ob[oA + ia] = acc[0] * fca + skb[oA + ia];
            ob[oB + ia] = acc[1] * fca + skb[oB + ia];
            ob[oA + ib] = acc[2] * fcb + skb[oA + ib];
            ob[oB + ib] = acc[3] * fcb + skb[oB + ib];
        }
    }
}

// ---------------------------------------------------------------------------
static __half* s_q = nullptr;
static __half* s_k = nullptr;
static __half* s_v = nullptr;

extern "C" void kernel_launch(void* const* d_in, const int* in_sizes, int n_in,
                              void* d_out, int out_size) {
    (void)in_sizes; (void)n_in; (void)out_size;
    static bool initialized = []() {
        void* p;
        cudaGetSymbolAddress(&p, g_q16); s_q = (__half*)p;
        cudaGetSymbolAddress(&p, g_k16); s_k = (__half*)p;
        cudaGetSymbolAddress(&p, g_v16); s_v = (__half*)p;
        cudaFuncSetAttribute(attn_kernel, cudaFuncAttributeMaxDynamicSharedMemorySize,
                             ATTN_SMEM);
        return true;
    }();
    (void)initialized;

    const float* gate  = (const float*)d_in[0];
    const float* skip  = (const float*)d_in[1];
    const float* Wq    = (const float*)d_in[2];
    const float* bq    = (const float*)d_in[3];
    const float* Wk    = (const float*)d_in[4];
    const float* bk    = (const float*)d_in[5];
    const float* Wv    = (const float*)d_in[6];
    const float* bv    = (const float*)d_in[7];
    const float* gamma = (const float*)d_in[8];
    float* out = (float*)d_out;

    const float LOG2E = 1.4426950408889634f;

    fused_conv<<<dim3(128, 1, NB), 256>>>(gate, skip, Wq, bq, Wk, bk, Wv, bv,
                                          s_q, s_k, s_v, LOG2E);
    attn_kernel<<<dim3(NTOK / TQ, NB), 256, ATTN_SMEM>>>(skip, gamma, out);
}

// round 16
// speedup vs baseline: 1.3784x; 1.0014x over previous
#include <cuda_runtime.h>
#include <cuda_fp16.h>
#include <cstdint>
#include <cstddef>

#define NTOK 4096
#define DQK  64
#define CVCH 256
#define NB   4
#define TQ   64
#define TK   64
#define NT   (NTOK / TK)   // 64

__device__ __align__(16) __half g_q16[NB * NTOK * 64];      // [b][n][64] hi
__device__ __align__(16) __half g_k16[NB * NTOK * 64];
__device__ __align__(16) __half g_v16[NB * NT * CVCH * TK]; // [b][t][c][64j]

__device__ __forceinline__ float fast_exp2(float x) {
    float r; asm("ex2.approx.ftz.f32 %0, %1;" : "=f"(r) : "f"(x)); return r;
}
__device__ __forceinline__ uint32_t smem_u32(const void* p) {
    uint32_t a;
    asm("{ .reg .u64 t; cvta.to.shared.u64 t, %1; cvt.u32.u64 %0, t; }" : "=r"(a) : "l"(p));
    return a;
}
#define MMA16(d, a0, a1, a2, a3, b0, b1) \
    asm volatile("mma.sync.aligned.m16n8k16.row.col.f32.f16.f16.f32 " \
        "{%0,%1,%2,%3}, {%4,%5,%6,%7}, {%8,%9}, {%0,%1,%2,%3};" \
        : "+f"((d)[0]), "+f"((d)[1]), "+f"((d)[2]), "+f"((d)[3]) \
        : "r"(a0), "r"(a1), "r"(a2), "r"(a3), "r"(b0), "r"(b1))
#define LDSM4(r0, r1, r2, r3, a) \
    asm volatile("ldmatrix.sync.aligned.m8n8.x4.shared.b16 {%0,%1,%2,%3},[%4];" \
        : "=r"(r0), "=r"(r1), "=r"(r2), "=r"(r3) : "r"(a))
#define LDSM4T(r0, r1, r2, r3, a) \
    asm volatile("ldmatrix.sync.aligned.m8n8.x4.trans.shared.b16 {%0,%1,%2,%3},[%4];" \
        : "=r"(r0), "=r"(r1), "=r"(r2), "=r"(r3) : "r"(a))
#define CP16(dst, src) \
    asm volatile("cp.async.cg.shared.global [%0], [%1], 16;" :: "r"(dst), "l"(src))
#define CPCOMMIT() asm volatile("cp.async.commit_group;")
#define CPWAITG(N) asm volatile("cp.async.wait_group %0;" :: "n"(N) : "memory")

// attn smem (half-index offsets unless noted). Rows stride 72 halves.
#define SQH 0        // [64][72]
#define SKB 4608     // 2 bufs x (KH 64x72)
#define SP  13824    // [64][72]
#define VBB 36864    // BYTE offset: 2 bufs x V[256][64] halves, 128B rows, swizzled
#define FOFFB 102400 // BYTE offset of float region
#define RM 0
#define FF 128
#define LR 192
#define ATTN_SMEM (FOFFB + 320 * 4)   // 103,680 B -> 2 CTAs/SM

// ---------------------------------------------------------------------------
// conv q/k: SINGLE-pass fp16 GEMM (q/k consumed at fp16 anyway).
// ---------------------------------------------------------------------------
__device__ __forceinline__
void conv_qk_body(__half* smc, float* sbias, const float* __restrict__ X,
                  const float* __restrict__ W, const float* __restrict__ bias,
                  __half* __restrict__ Y, int C, float scale, int b, int n0) {
    const int WH = 4352;
    const int tid = threadIdx.x, lane = tid & 31, w = tid >> 5;
    const int gid = lane >> 2, tig = lane & 3, lr = lane & 15, lc = (lane >> 4) << 3;
    const uint32_t sb = smem_u32(smc);
    if (tid < 64) sbias[tid] = bias[tid];
    float acc[8][4];
    #pragma unroll
    for (int i = 0; i < 8; i++)
        #pragma unroll
        for (int e = 0; e < 4; e++) acc[i][e] = 0.f;

    for (int c0 = 0; c0 < C; c0 += 32) {
        __syncthreads();
        #pragma unroll
        for (int p = 0; p < 4; p++) {
            int idx = tid + p * 256, cc = idx >> 5, n4 = (idx & 31) << 2;
            float4 x = *reinterpret_cast<const float4*>(X + ((size_t)b * C + c0 + cc) * NTOK + n0 + n4);
            __half2 p0 = __floats2half2_rn(x.x, x.y), p1 = __floats2half2_rn(x.z, x.w);
            uint2 u; u.x = *(uint32_t*)&p0; u.y = *(uint32_t*)&p1;
            *reinterpret_cast<uint2*>(smc + cc * 136 + n4) = u;
        }
        #pragma unroll
        for (int p = 0; p < 2; p++) {
            int idx = tid + p * 256, oo = idx >> 3, c4 = (idx & 7) << 2;
            float4 x = *reinterpret_cast<const float4*>(W + (size_t)oo * C + c0 + c4);
            __half2 p0 = __floats2half2_rn(x.x, x.y), p1 = __floats2half2_rn(x.z, x.w);
            uint2 u; u.x = *(uint32_t*)&p0; u.y = *(uint32_t*)&p1;
            *reinterpret_cast<uint2*>(smc + WH + oo * 40 + c4) = u;
        }
        __syncthreads();
        #pragma unroll
        for (int ks = 0; ks < 2; ks++) {
            uint32_t a0, a1, a2, a3;
            uint32_t ax = sb + 2u * (((ks << 4) + (lane & 7) + ((lane >> 4) << 3)) * 136
                                     + (w << 4) + (((lane >> 3) & 1) << 3));
            LDSM4T(a0, a1, a2, a3, ax);
            #pragma unroll
            for (int p = 0; p < 4; p++) {
                uint32_t b0, b1, b2, b3;
                uint32_t aw = sb + 2u * (WH + ((p << 4) + lr) * 40 + (ks << 4) + lc);
                LDSM4(b0, b1, b2, b3, aw);
                MMA16(acc[2 * p],     a0, a1, a2, a3, b0, b2);
                MMA16(acc[2 * p + 1], a0, a1, a2, a3, b1, b3);
            }
        }
    }
    const int tok0 = n0 + (w << 4) + gid;
    #pragma unroll
    for (int nt = 0; nt < 8; nt++) {
        const int c = nt * 8 + 2 * tig;
        float b0s = sbias[c], b1s = sbias[c + 1];
        #pragma unroll
        for (int rr = 0; rr < 2; rr++) {
            float v0 = (acc[nt][2 * rr] + b0s) * scale;
            float v1 = (acc[nt][2 * rr + 1] + b1s) * scale;
            __half2 hh = __floats2half2_rn(v0, v1);
            *(uint32_t*)(Y + ((size_t)b * NTOK + tok0 + rr * 8) * 64 + c) = *(uint32_t*)&hh;
        }
    }
}

__device__ __forceinline__
void conv_v_body(__half* smc, float* sbias, const float* __restrict__ X,
                 const float* __restrict__ W, const float* __restrict__ bias,
                 __half* __restrict__ Y, int C, int b, int o0, int n0) {
    const int WHo = 4352;
    const int tid = threadIdx.x, lane = tid & 31, w = tid >> 5;
    const int gid = lane >> 2, tig = lane & 3, lr = lane & 15, lc = (lane >> 4) << 3;
    const uint32_t sb = smem_u32(smc);
    if (tid < 128) sbias[tid] = bias[o0 + tid];
    float acc[16][4];
    #pragma unroll
    for (int i = 0; i < 16; i++)
        #pragma unroll
        for (int e = 0; e < 4; e++) acc[i][e] = 0.f;

    for (int c0 = 0; c0 < C; c0 += 32) {
        __syncthreads();
        #pragma unroll
        for (int p = 0; p < 4; p++) {
            int idx = tid + p * 256, cc = idx >> 5, n4 = (idx & 31) << 2;
            float4 x = *reinterpret_cast<const float4*>(X + ((size_t)b * C + c0 + cc) * NTOK + n0 + n4);
            __half2 p0 = __floats2half2_rn(x.x, x.y), p1 = __floats2half2_rn(x.z, x.w);
            uint2 u; u.x = *(uint32_t*)&p0; u.y = *(uint32_t*)&p1;
            *reinterpret_cast<uint2*>(smc + cc * 136 + n4) = u;
        }
        #pragma unroll
        for (int p = 0; p < 4; p++) {
            int idx = tid + p * 256, oo = idx >> 3, c4 = (idx & 7) << 2;
            float4 x = *reinterpret_cast<const float4*>(W + (size_t)(o0 + oo) * C + c0 + c4);
            __half2 p0 = __floats2half2_rn(x.x, x.y), p1 = __floats2half2_rn(x.z, x.w);
            uint2 u; u.x = *(uint32_t*)&p0; u.y = *(uint32_t*)&p1;
            *reinterpret_cast<uint2*>(smc + WHo + oo * 40 + c4) = u;
        }
        __syncthreads();
        #pragma unroll
        for (int ks = 0; ks < 2; ks++) {
            uint32_t a0, a1, a2, a3;
            LDSM4(a0, a1, a2, a3, sb + 2u * (WHo + ((w << 4) + lr) * 40 + (ks << 4) + lc));
            #pragma unroll
            for (int tp = 0; tp < 8; tp++) {
                uint32_t v0, v1, v2, v3;
                uint32_t ax = sb + 2u * (((ks << 4) + (lane & 7) + ((lane >> 4) << 3)) * 136
                                         + (tp << 4) + (((lane >> 3) & 1) << 3));
                LDSM4T(v0, v1, v2, v3, ax);
                MMA16(acc[2 * tp],     a0, a1, a2, a3, v0, v2);
                MMA16(acc[2 * tp + 1], a0, a1, a2, a3, v1, v3);
            }
        }
    }
    const int orow = (w << 4) + gid;
    float br0 = sbias[orow], br1 = sbias[orow + 8];
    __half* vbo = Y + ((size_t)b * NT + (n0 >> 6)) * CVCH * 64;
    #pragma unroll
    for (int nt = 0; nt < 16; nt++) {
        int tokoff = nt * 8 + 2 * tig;
        int tadd = tokoff >> 6, j = tokoff & 63;
        __half2 h0 = __floats2half2_rn(acc[nt][0] + br0, acc[nt][1] + br0);
        __half2 h1 = __floats2half2_rn(acc[nt][2] + br1, acc[nt][3] + br1);
        __half* p0 = vbo + ((size_t)tadd * CVCH + o0 + orow) * 64 + j;
        *(uint32_t*)p0 = *(uint32_t*)&h0;
        *(uint32_t*)(p0 + 8 * 64) = *(uint32_t*)&h1;
    }
}

__global__ __launch_bounds__(256)
void fused_conv(const float* __restrict__ gate, const float* __restrict__ skip,
                const float* __restrict__ Wq, const float* __restrict__ bq,
                const float* __restrict__ Wk, const float* __restrict__ bk,
                const float* __restrict__ Wv, const float* __restrict__ bv,
                __half* __restrict__ q, __half* __restrict__ k,
                __half* __restrict__ v, float scale) {
    __shared__ __half smc[9472];
    __shared__ float sbias[128];
    const int gx = blockIdx.x, b = blockIdx.z;
    if (gx < 32) {
        conv_qk_body(smc, sbias, gate, Wq, bq, q, 512, scale, b, gx << 7);
    } else if (gx < 64) {
        conv_qk_body(smc, sbias, skip, Wk, bk, k, 256, 1.0f, b, (gx - 32) << 7);
    } else {
        const int vx = gx - 64;
        conv_v_body(smc, sbias, skip, Wv, bv, v, 256, b,
                    (vx >> 5) << 7, (vx & 31) << 7);
    }
}

// ---------------------------------------------------------------------------
// Flash attention: single-pass fp16 S, K+V double-buffered, 3 syncs/tile.
// ---------------------------------------------------------------------------
__global__ __launch_bounds__(256, 2)
void attn_kernel(const float* __restrict__ skip, const float* __restrict__ gamma,
                 float* __restrict__ out) {
    extern __shared__ __align__(16) char sm[];
    __half* smh = (__half*)sm;
    float* smf = (float*)(sm + FOFFB);
    const uint32_t sb = smem_u32(sm);
    const int tid = threadIdx.x, lane = tid & 31, w = tid >> 5;
    const int gid = lane >> 2, tig = lane & 3, lr = lane & 15, lc = (lane >> 4) << 3;
    const int r0 = (w & 3) << 4;
    const int ch = w >> 2;
    const int rq = (w & 1) << 5, cq = (w >> 1) << 6;
    const int b = blockIdx.y, i0 = blockIdx.x * TQ;
    const int row0 = r0 + gid, row1 = row0 + 8;

    const __half* qb = g_q16 + (size_t)b * NTOK * 64;
    const __half* kb = g_k16 + (size_t)b * NTOK * 64;
    const __half* vbg = g_v16 + (size_t)b * NT * CVCH * TK;

    // prologue: group0 = {Q, K0}, group1 = {V0}
    #pragma unroll
    for (int p = 0; p < 2; p++) {
        int chunk = tid + p * 256, row = chunk >> 3, c8 = chunk & 7;
        CP16(sb + 2u * (SQH + row * 72 + c8 * 8), qb + (size_t)(i0 + row) * 64 + c8 * 8);
    }
    #pragma unroll
    for (int p = 0; p < 2; p++) {
        int chunk = tid + p * 256, row = chunk >> 3, c8 = chunk & 7;
        CP16(sb + 2u * (SKB + row * 72 + c8 * 8), kb + (size_t)row * 64 + c8 * 8);
    }
    CPCOMMIT();
    #pragma unroll
    for (int p = 0; p < 8; p++) {
        int chunk = tid + p * 256, row = chunk >> 3, cb = chunk & 7;
        uint32_t d = sb + VBB + row * 128 + (((uint32_t)(cb ^ (row & 7))) << 4);
        CP16(d, vbg + (size_t)row * 64 + cb * 8);
    }
    CPCOMMIT();

    float oacc[16][4];
    #pragma unroll
    for (int t = 0; t < 16; t++)
        #pragma unroll
        for (int e = 0; e < 4; e++) oacc[t][e] = 0.f;
    float rm0 = -1e30f, rm1 = -1e30f, lsum0 = 0.f, lsum1 = 0.f;

    for (int t = 0; t < NT; t++) {
        const int buf = t & 1;
        CPWAITG(1);        // K(t) (+ all older) ready; V(t) may pend
        __syncthreads();   // syncT: K(t) visible; PV(t-1) globally done

        // S = qh.kh (single pass), 4 independent acc chains
        const int kh = SKB + buf * 4608;
        float sacc[4][4];
        #pragma unroll
        for (int tt = 0; tt < 4; tt++)
            #pragma unroll
            for (int e = 0; e < 4; e++) sacc[tt][e] = 0.f;
        #pragma unroll
        for (int kk = 0; kk < 4; kk++) {
            uint32_t ah0, ah1, ah2, ah3;
            uint32_t aq = sb + 2u * (SQH + (r0 + lr) * 72 + kk * 16 + lc);
            LDSM4(ah0, ah1, ah2, ah3, aq);
            uint32_t bh[2][4];
            #pragma unroll
            for (int tp = 0; tp < 2; tp++) {
                uint32_t ak = sb + 2u * (kh + (ch * 32 + tp * 16 + lr) * 72 + kk * 16 + lc);
                LDSM4(bh[tp][0], bh[tp][1], bh[tp][2], bh[tp][3], ak);
            }
            MMA16(sacc[0], ah0, ah1, ah2, ah3, bh[0][0], bh[0][2]);
            MMA16(sacc[1], ah0, ah1, ah2, ah3, bh[0][1], bh[0][3]);
            MMA16(sacc[2], ah0, ah1, ah2, ah3, bh[1][0], bh[1][2]);
            MMA16(sacc[3], ah0, ah1, ah2, ah3, bh[1][1], bh[1][3]);
        }
        float mx0 = -1e30f, mx1 = -1e30f;
        #pragma unroll
        for (int tt = 0; tt < 4; tt++) {
            mx0 = fmaxf(mx0, fmaxf(sacc[tt][0], sacc[tt][1]));
            mx1 = fmaxf(mx1, fmaxf(sacc[tt][2], sacc[tt][3]));
        }
        mx0 = fmaxf(mx0, __shfl_xor_sync(0xFFFFFFFFu, mx0, 1));
        mx0 = fmaxf(mx0, __shfl_xor_sync(0xFFFFFFFFu, mx0, 2));
        mx1 = fmaxf(mx1, __shfl_xor_sync(0xFFFFFFFFu, mx1, 1));
        mx1 = fmaxf(mx1, __shfl_xor_sync(0xFFFFFFFFu, mx1, 2));
        if (tig == 0) {
            smf[RM + row0 * 2 + ch] = mx0;
            smf[RM + row1 * 2 + ch] = mx1;
        }
        __syncthreads();   // syncA: RM visible

        // prefetch next tile (K group first, then V group)
        if (t + 1 < NT) {
            const int kbase = SKB + ((t + 1) & 1) * 4608;
            #pragma unroll
            for (int p = 0; p < 2; p++) {
                int chunk = tid + p * 256, row = chunk >> 3, c8 = chunk & 7;
                CP16(sb + 2u * (kbase + row * 72 + c8 * 8),
                     kb + (size_t)((t + 1) * TK + row) * 64 + c8 * 8);
            }
            CPCOMMIT();
            const __half* vt = vbg + (size_t)(t + 1) * CVCH * TK;
            const uint32_t vbase = VBB + (uint32_t)((t + 1) & 1) * 32768u;
            #pragma unroll
            for (int p = 0; p < 8; p++) {
                int chunk = tid + p * 256, row = chunk >> 3, cb = chunk & 7;
                uint32_t d = sb + vbase + row * 128 + (((uint32_t)(cb ^ (row & 7))) << 4);
                CP16(d, vt + (size_t)row * 64 + cb * 8);
            }
            CPCOMMIT();
        }

        // online softmax -> P fp16
        float mn0 = fmaxf(rm0, fmaxf(smf[RM + row0 * 2], smf[RM + row0 * 2 + 1]));
        float mn1 = fmaxf(rm1, fmaxf(smf[RM + row1 * 2], smf[RM + row1 * 2 + 1]));
        float f0 = fast_exp2(rm0 - mn0), f1 = fast_exp2(rm1 - mn1);
        rm0 = mn0; rm1 = mn1;
        if (tig == 0 && ch == 0) { smf[FF + row0] = f0; smf[FF + row1] = f1; }
        float ps0 = 0.f, ps1 = 0.f;
        #pragma unroll
        for (int tt = 0; tt < 4; tt++) {
            float p00 = fast_exp2(sacc[tt][0] - mn0);
            float p01 = fast_exp2(sacc[tt][1] - mn0);
            float p10 = fast_exp2(sacc[tt][2] - mn1);
            float p11 = fast_exp2(sacc[tt][3] - mn1);
            ps0 += p00 + p01; ps1 += p10 + p11;
            __half2 h0 = __floats2half2_rn(p00, p01);
            __half2 h1 = __floats2half2_rn(p10, p11);
            const int cc = ch * 32 + tt * 8 + 2 * tig;
            *(uint32_t*)(smh + SP + row0 * 72 + cc) = *(uint32_t*)&h0;
            *(uint32_t*)(smh + SP + row1 * 72 + cc) = *(uint32_t*)&h1;
        }
        lsum0 = lsum0 * f0 + ps0;
        lsum1 = lsum1 * f1 + ps1;
        if (t + 1 < NT) { CPWAITG(2); } else { CPWAITG(0); }  // V(t) done
        __syncthreads();   // syncB: P + V(t) visible

        // rescale O (skipped when no row max changed), then O += P.V^T
        float fa0 = smf[FF + rq + gid], fa1 = smf[FF + rq + gid + 8];
        float fb0 = smf[FF + rq + 16 + gid], fb1 = smf[FF + rq + 16 + gid + 8];
        if (!__all_sync(0xFFFFFFFFu,
                        (fa0 == 1.f) & (fa1 == 1.f) & (fb0 == 1.f) & (fb1 == 1.f))) {
            #pragma unroll
            for (int nt = 0; nt < 8; nt++) {
                oacc[nt][0] *= fa0; oacc[nt][1] *= fa0;
                oacc[nt][2] *= fa1; oacc[nt][3] *= fa1;
                oacc[8 + nt][0] *= fb0; oacc[8 + nt][1] *= fb0;
                oacc[8 + nt][2] *= fb1; oacc[8 + nt][3] *= fb1;
            }
        }
        const uint32_t vbuf = VBB + (uint32_t)buf * 32768u;
        #pragma unroll
        for (int kk = 0; kk < 4; kk++) {
            uint32_t pa0, pa1, pa2, pa3, qa0, qa1, qa2, qa3;
            uint32_t ap = sb + 2u * (SP + (rq + lr) * 72 + kk * 16 + lc);
            LDSM4(pa0, pa1, pa2, pa3, ap);
            LDSM4(qa0, qa1, qa2, qa3, ap + 2u * (16 * 72));
            const uint32_t cb = (uint32_t)(kk * 2 + (lc >> 3));
            #pragma unroll
            for (int np = 0; np < 4; np++) {
                const int vrow = cq + np * 16 + lr;
                uint32_t va = sb + vbuf + vrow * 128 + ((cb ^ (uint32_t)(vrow & 7)) << 4);
                uint32_t v0, v1, v2, v3;
                LDSM4(v0, v1, v2, v3, va);
                MMA16(oacc[2 * np],         pa0, pa1, pa2, pa3, v0, v2);
                MMA16(oacc[2 * np + 1],     pa0, pa1, pa2, pa3, v1, v3);
                MMA16(oacc[8 + 2 * np],     qa0, qa1, qa2, qa3, v0, v2);
                MMA16(oacc[8 + 2 * np + 1], qa0, qa1, qa2, qa3, v1, v3);
            }
        }
    }

    // final l reduction + epilogue
    lsum0 += __shfl_xor_sync(0xFFFFFFFFu, lsum0, 1);
    lsum0 += __shfl_xor_sync(0xFFFFFFFFu, lsum0, 2);
    lsum1 += __shfl_xor_sync(0xFFFFFFFFu, lsum1, 1);
    lsum1 += __shfl_xor_sync(0xFFFFFFFFu, lsum1, 2);
    __syncthreads();
    if (tig == 0) {
        smf[LR + row0 * 2 + ch] = lsum0;
        smf[LR + row1 * 2 + ch] = lsum1;
    }
    __syncthreads();

    const float gm = __ldg(gamma);
    const float* skb = skip + (size_t)b * CVCH * NTOK;
    float* ob = out + (size_t)b * CVCH * NTOK;
    #pragma unroll
    for (int mt = 0; mt < 2; mt++) {
        const int ra = rq + mt * 16 + gid, rb = ra + 8;
        const float fca = gm / (smf[LR + ra * 2] + smf[LR + ra * 2 + 1]);
        const float fcb = gm / (smf[LR + rb * 2] + smf[LR + rb * 2 + 1]);
        const int ia = i0 + ra, ib = i0 + rb;
        #pragma unroll
        for (int nt = 0; nt < 8; nt++) {
            const int c = cq + nt * 8 + 2 * tig;
            const size_t oA = (size_t)c * NTOK, oB = (size_t)(c + 1) * NTOK;
            const float* acc = oacc[mt * 8 + nt];
            ob[oA + ia] = acc[0] * fca + skb[oA + ia];
            ob[oB + ia] = acc[1] * fca + skb[oB + ia];
            ob[oA + ib] = acc[2] * fcb + skb[oA + ib];
            ob[oB + ib] = acc[3] * fcb + skb[oB + ib];
        }
    }
}

// ---------------------------------------------------------------------------
static __half* s_q = nullptr;
static __half* s_k = nullptr;
static __half* s_v = nullptr;

extern "C" void kernel_launch(void* const* d_in, const int* in_sizes, int n_in,
                              void* d_out, int out_size) {
    (void)in_sizes; (void)n_in; (void)out_size;
    static bool initialized = []() {
        void* p;
        cudaGetSymbolAddress(&p, g_q16); s_q = (__half*)p;
        cudaGetSymbolAddress(&p, g_k16); s_k = (__half*)p;
        cudaGetSymbolAddress(&p, g_v16); s_v = (__half*)p;
        cudaFuncSetAttribute(attn_kernel, cudaFuncAttributeMaxDynamicSharedMemorySize,
                             ATTN_SMEM);
        return true;
    }();
    (void)initialized;

    const float* gate  = (const float*)d_in[0];
    const float* skip  = (const float*)d_in[1];
    const float* Wq    = (const float*)d_in[2];
    const float* bq    = (const float*)d_in[3];
    const float* Wk    = (const float*)d_in[4];
    const float* bk    = (const float*)d_in[5];
    const float* Wv    = (const float*)d_in[6];
    const float* bv    = (const float*)d_in[7];
    const float* gamma = (const float*)d_in[8];
    float* out = (float*)d_out;

    const float LOG2E = 1.4426950408889634f;

    fused_conv<<<dim3(128, 1, NB), 256>>>(gate, skip, Wq, bq, Wk, bk, Wv, bv,
                                          s_q, s_k, s_v, LOG2E);
    attn_kernel<<<dim3(NTOK / TQ, NB), 256, ATTN_SMEM>>>(skip, gamma, out);
}

// round 17
// speedup vs baseline: 1.4274x; 1.0355x over previous
#include <cuda_runtime.h>
#include <cuda_fp16.h>
#include <cstdint>
#include <cstddef>

#define NTOK 4096
#define DQK  64
#define CVCH 256
#define NB   4
#define TQ   64
#define TK   64
#define NT   (NTOK / TK)   // 64

__device__ __align__(16) __half g_q16[NB * NTOK * 64];      // [b][n][64]
__device__ __align__(16) __half g_k16[NB * NTOK * 64];
__device__ __align__(16) __half g_v16[NB * NT * CVCH * TK]; // [b][t][c][64j]

__device__ __forceinline__ float fast_exp2(float x) {
    float r; asm("ex2.approx.ftz.f32 %0, %1;" : "=f"(r) : "f"(x)); return r;
}
__device__ __forceinline__ uint32_t smem_u32(const void* p) {
    uint32_t a;
    asm("{ .reg .u64 t; cvta.to.shared.u64 t, %1; cvt.u32.u64 %0, t; }" : "=r"(a) : "l"(p));
    return a;
}
#define MMA16(d, a0, a1, a2, a3, b0, b1) \
    asm volatile("mma.sync.aligned.m16n8k16.row.col.f32.f16.f16.f32 " \
        "{%0,%1,%2,%3}, {%4,%5,%6,%7}, {%8,%9}, {%0,%1,%2,%3};" \
        : "+f"((d)[0]), "+f"((d)[1]), "+f"((d)[2]), "+f"((d)[3]) \
        : "r"(a0), "r"(a1), "r"(a2), "r"(a3), "r"(b0), "r"(b1))
#define LDSM4(r0, r1, r2, r3, a) \
    asm volatile("ldmatrix.sync.aligned.m8n8.x4.shared.b16 {%0,%1,%2,%3},[%4];" \
        : "=r"(r0), "=r"(r1), "=r"(r2), "=r"(r3) : "r"(a))
#define LDSM4T(r0, r1, r2, r3, a) \
    asm volatile("ldmatrix.sync.aligned.m8n8.x4.trans.shared.b16 {%0,%1,%2,%3},[%4];" \
        : "=r"(r0), "=r"(r1), "=r"(r2), "=r"(r3) : "r"(a))
#define CP16(dst, src) \
    asm volatile("cp.async.cg.shared.global [%0], [%1], 16;" :: "r"(dst), "l"(src))
#define CPCOMMIT() asm volatile("cp.async.commit_group;")
#define CPWAITG(N) asm volatile("cp.async.wait_group %0;" :: "n"(N) : "memory")

// attn smem (half-index offsets unless noted). Rows stride 72 halves.
// R15 layout: K double-buffered, V single-buffered.
#define SQH 0        // [64][72]
#define SKB 4608     // 2 bufs x (KH 64x72)
#define SP  13824    // [64][72]
#define VBB 36864    // BYTE offset: V [256][64] halves, 128B rows, XOR-swizzled
#define FOFFB 69632  // BYTE offset of float region
#define RM 0
#define FF 128
#define LR 192
#define ATTN_SMEM (FOFFB + 320 * 4)   // 70,912 B -> 2 CTAs/SM

// ---------------------------------------------------------------------------
// conv q/k: single-pass fp16 GEMM (R16, measured).
// ---------------------------------------------------------------------------
__device__ __forceinline__
void conv_qk_body(__half* smc, float* sbias, const float* __restrict__ X,
                  const float* __restrict__ W, const float* __restrict__ bias,
                  __half* __restrict__ Y, int C, float scale, int b, int n0) {
    const int WH = 4352;
    const int tid = threadIdx.x, lane = tid & 31, w = tid >> 5;
    const int gid = lane >> 2, tig = lane & 3, lr = lane & 15, lc = (lane >> 4) << 3;
    const uint32_t sb = smem_u32(smc);
    if (tid < 64) sbias[tid] = bias[tid];
    float acc[8][4];
    #pragma unroll
    for (int i = 0; i < 8; i++)
        #pragma unroll
        for (int e = 0; e < 4; e++) acc[i][e] = 0.f;

    for (int c0 = 0; c0 < C; c0 += 32) {
        __syncthreads();
        #pragma unroll
        for (int p = 0; p < 4; p++) {
            int idx = tid + p * 256, cc = idx >> 5, n4 = (idx & 31) << 2;
            float4 x = *reinterpret_cast<const float4*>(X + ((size_t)b * C + c0 + cc) * NTOK + n0 + n4);
            __half2 p0 = __floats2half2_rn(x.x, x.y), p1 = __floats2half2_rn(x.z, x.w);
            uint2 u; u.x = *(uint32_t*)&p0; u.y = *(uint32_t*)&p1;
            *reinterpret_cast<uint2*>(smc + cc * 136 + n4) = u;
        }
        #pragma unroll
        for (int p = 0; p < 2; p++) {
            int idx = tid + p * 256, oo = idx >> 3, c4 = (idx & 7) << 2;
            float4 x = *reinterpret_cast<const float4*>(W + (size_t)oo * C + c0 + c4);
            __half2 p0 = __floats2half2_rn(x.x, x.y), p1 = __floats2half2_rn(x.z, x.w);
            uint2 u; u.x = *(uint32_t*)&p0; u.y = *(uint32_t*)&p1;
            *reinterpret_cast<uint2*>(smc + WH + oo * 40 + c4) = u;
        }
        __syncthreads();
        #pragma unroll
        for (int ks = 0; ks < 2; ks++) {
            uint32_t a0, a1, a2, a3;
            uint32_t ax = sb + 2u * (((ks << 4) + (lane & 7) + ((lane >> 4) << 3)) * 136
                                     + (w << 4) + (((lane >> 3) & 1) << 3));
            LDSM4T(a0, a1, a2, a3, ax);
            #pragma unroll
            for (int p = 0; p < 4; p++) {
                uint32_t b0, b1, b2, b3;
                uint32_t aw = sb + 2u * (WH + ((p << 4) + lr) * 40 + (ks << 4) + lc);
                LDSM4(b0, b1, b2, b3, aw);
                MMA16(acc[2 * p],     a0, a1, a2, a3, b0, b2);
                MMA16(acc[2 * p + 1], a0, a1, a2, a3, b1, b3);
            }
        }
    }
    const int tok0 = n0 + (w << 4) + gid;
    #pragma unroll
    for (int nt = 0; nt < 8; nt++) {
        const int c = nt * 8 + 2 * tig;
        float b0s = sbias[c], b1s = sbias[c + 1];
        #pragma unroll
        for (int rr = 0; rr < 2; rr++) {
            float v0 = (acc[nt][2 * rr] + b0s) * scale;
            float v1 = (acc[nt][2 * rr + 1] + b1s) * scale;
            __half2 hh = __floats2half2_rn(v0, v1);
            *(uint32_t*)(Y + ((size_t)b * NTOK + tok0 + rr * 8) * 64 + c) = *(uint32_t*)&hh;
        }
    }
}

__device__ __forceinline__
void conv_v_body(__half* smc, float* sbias, const float* __restrict__ X,
                 const float* __restrict__ W, const float* __restrict__ bias,
                 __half* __restrict__ Y, int C, int b, int o0, int n0) {
    const int WHo = 4352;
    const int tid = threadIdx.x, lane = tid & 31, w = tid >> 5;
    const int gid = lane >> 2, tig = lane & 3, lr = lane & 15, lc = (lane >> 4) << 3;
    const uint32_t sb = smem_u32(smc);
    if (tid < 128) sbias[tid] = bias[o0 + tid];
    float acc[16][4];
    #pragma unroll
    for (int i = 0; i < 16; i++)
        #pragma unroll
        for (int e = 0; e < 4; e++) acc[i][e] = 0.f;

    for (int c0 = 0; c0 < C; c0 += 32) {
        __syncthreads();
        #pragma unroll
        for (int p = 0; p < 4; p++) {
            int idx = tid + p * 256, cc = idx >> 5, n4 = (idx & 31) << 2;
            float4 x = *reinterpret_cast<const float4*>(X + ((size_t)b * C + c0 + cc) * NTOK + n0 + n4);
            __half2 p0 = __floats2half2_rn(x.x, x.y), p1 = __floats2half2_rn(x.z, x.w);
            uint2 u; u.x = *(uint32_t*)&p0; u.y = *(uint32_t*)&p1;
            *reinterpret_cast<uint2*>(smc + cc * 136 + n4) = u;
        }
        #pragma unroll
        for (int p = 0; p < 4; p++) {
            int idx = tid + p * 256, oo = idx >> 3, c4 = (idx & 7) << 2;
            float4 x = *reinterpret_cast<const float4*>(W + (size_t)(o0 + oo) * C + c0 + c4);
            __half2 p0 = __floats2half2_rn(x.x, x.y), p1 = __floats2half2_rn(x.z, x.w);
            uint2 u; u.x = *(uint32_t*)&p0; u.y = *(uint32_t*)&p1;
            *reinterpret_cast<uint2*>(smc + WHo + oo * 40 + c4) = u;
        }
        __syncthreads();
        #pragma unroll
        for (int ks = 0; ks < 2; ks++) {
            uint32_t a0, a1, a2, a3;
            LDSM4(a0, a1, a2, a3, sb + 2u * (WHo + ((w << 4) + lr) * 40 + (ks << 4) + lc));
            #pragma unroll
            for (int tp = 0; tp < 8; tp++) {
                uint32_t v0, v1, v2, v3;
                uint32_t ax = sb + 2u * (((ks << 4) + (lane & 7) + ((lane >> 4) << 3)) * 136
                                         + (tp << 4) + (((lane >> 3) & 1) << 3));
                LDSM4T(v0, v1, v2, v3, ax);
                MMA16(acc[2 * tp],     a0, a1, a2, a3, v0, v2);
                MMA16(acc[2 * tp + 1], a0, a1, a2, a3, v1, v3);
            }
        }
    }
    const int orow = (w << 4) + gid;
    float br0 = sbias[orow], br1 = sbias[orow + 8];
    __half* vbo = Y + ((size_t)b * NT + (n0 >> 6)) * CVCH * 64;
    #pragma unroll
    for (int nt = 0; nt < 16; nt++) {
        int tokoff = nt * 8 + 2 * tig;
        int tadd = tokoff >> 6, j = tokoff & 63;
        __half2 h0 = __floats2half2_rn(acc[nt][0] + br0, acc[nt][1] + br0);
        __half2 h1 = __floats2half2_rn(acc[nt][2] + br1, acc[nt][3] + br1);
        __half* p0 = vbo + ((size_t)tadd * CVCH + o0 + orow) * 64 + j;
        *(uint32_t*)p0 = *(uint32_t*)&h0;
        *(uint32_t*)(p0 + 8 * 64) = *(uint32_t*)&h1;
    }
}

__global__ __launch_bounds__(256)
void fused_conv(const float* __restrict__ gate, const float* __restrict__ skip,
                const float* __restrict__ Wq, const float* __restrict__ bq,
                const float* __restrict__ Wk, const float* __restrict__ bk,
                const float* __restrict__ Wv, const float* __restrict__ bv,
                __half* __restrict__ q, __half* __restrict__ k,
                __half* __restrict__ v, float scale) {
    __shared__ __half smc[9472];
    __shared__ float sbias[128];
    const int gx = blockIdx.x, b = blockIdx.z;
    if (gx < 32) {
        conv_qk_body(smc, sbias, gate, Wq, bq, q, 512, scale, b, gx << 7);
    } else if (gx < 64) {
        conv_qk_body(smc, sbias, skip, Wk, bk, k, 256, 1.0f, b, (gx - 32) << 7);
    } else {
        const int vx = gx - 64;
        conv_v_body(smc, sbias, skip, Wv, bv, v, 256, b,
                    (vx >> 5) << 7, (vx & 31) << 7);
    }
}

// ---------------------------------------------------------------------------
// Flash attention: EXACT R15 schedule (measured 189.9 us), stride-64 q/k.
// Single-pass fp16 S; K double-buffered; V single-buffered; 4 syncs/tile.
// ---------------------------------------------------------------------------
__global__ __launch_bounds__(256, 2)
void attn_kernel(const float* __restrict__ skip, const float* __restrict__ gamma,
                 float* __restrict__ out) {
    extern __shared__ __align__(16) char sm[];
    __half* smh = (__half*)sm;
    float* smf = (float*)(sm + FOFFB);
    const uint32_t sb = smem_u32(sm);
    const int tid = threadIdx.x, lane = tid & 31, w = tid >> 5;
    const int gid = lane >> 2, tig = lane & 3, lr = lane & 15, lc = (lane >> 4) << 3;
    const int r0 = (w & 3) << 4;
    const int ch = w >> 2;
    const int rq = (w & 1) << 5, cq = (w >> 1) << 6;
    const int b = blockIdx.y, i0 = blockIdx.x * TQ;
    const int row0 = r0 + gid, row1 = row0 + 8;

    const __half* qb = g_q16 + (size_t)b * NTOK * 64;
    const __half* kb = g_k16 + (size_t)b * NTOK * 64;
    const __half* vbg = g_v16 + (size_t)b * NT * CVCH * TK;

    // prologue: group1 = Q, group2 = K(0)
    #pragma unroll
    for (int p = 0; p < 2; p++) {
        int chunk = tid + p * 256, row = chunk >> 3, c8 = chunk & 7;
        CP16(sb + 2u * (SQH + row * 72 + c8 * 8), qb + (size_t)(i0 + row) * 64 + c8 * 8);
    }
    CPCOMMIT();
    #pragma unroll
    for (int p = 0; p < 2; p++) {
        int chunk = tid + p * 256, row = chunk >> 3, c8 = chunk & 7;
        CP16(sb + 2u * (SKB + row * 72 + c8 * 8), kb + (size_t)row * 64 + c8 * 8);
    }
    CPCOMMIT();

    float oacc[16][4];
    #pragma unroll
    for (int t = 0; t < 16; t++)
        #pragma unroll
        for (int e = 0; e < 4; e++) oacc[t][e] = 0.f;
    float rm0 = -1e30f, rm1 = -1e30f, lsum0 = 0.f, lsum1 = 0.f;

    for (int t = 0; t < NT; t++) {
        const int buf = t & 1;
        __syncthreads();   // PV(t-1) complete: vbuf + kbuf[(t+1)&1] free
        // issue V(t) (group), then K(t+1) (group)
        {
            const __half* vt = vbg + (size_t)t * CVCH * TK;
            #pragma unroll
            for (int p = 0; p < 8; p++) {
                int chunk = tid + p * 256, row = chunk >> 3, cb = chunk & 7;
                uint32_t d = sb + VBB + row * 128 + (((uint32_t)(cb ^ (row & 7))) << 4);
                CP16(d, vt + (size_t)row * 64 + cb * 8);
            }
            CPCOMMIT();
            const int tn = (t + 1) & (NT - 1);
            const int kbase = SKB + ((t + 1) & 1) * 4608;
            #pragma unroll
            for (int p = 0; p < 2; p++) {
                int chunk = tid + p * 256, row = chunk >> 3, c8 = chunk & 7;
                CP16(sb + 2u * (kbase + row * 72 + c8 * 8),
                     kb + (size_t)(tn * TK + row) * 64 + c8 * 8);
            }
            CPCOMMIT();
        }
        CPWAITG(2);        // K(t) (and Q) ready; V(t), K(t+1) may pend
        __syncthreads();

        // S = qh.kh (single pass), 4 independent acc chains
        const int kh = SKB + buf * 4608;
        float sacc[4][4];
        #pragma unroll
        for (int tt = 0; tt < 4; tt++)
            #pragma unroll
            for (int e = 0; e < 4; e++) sacc[tt][e] = 0.f;
        #pragma unroll
        for (int kk = 0; kk < 4; kk++) {
            uint32_t ah0, ah1, ah2, ah3;
            uint32_t aq = sb + 2u * (SQH + (r0 + lr) * 72 + kk * 16 + lc);
            LDSM4(ah0, ah1, ah2, ah3, aq);
            uint32_t bh[2][4];
            #pragma unroll
            for (int tp = 0; tp < 2; tp++) {
                uint32_t ak = sb + 2u * (kh + (ch * 32 + tp * 16 + lr) * 72 + kk * 16 + lc);
                LDSM4(bh[tp][0], bh[tp][1], bh[tp][2], bh[tp][3], ak);
            }
            MMA16(sacc[0], ah0, ah1, ah2, ah3, bh[0][0], bh[0][2]);
            MMA16(sacc[1], ah0, ah1, ah2, ah3, bh[0][1], bh[0][3]);
            MMA16(sacc[2], ah0, ah1, ah2, ah3, bh[1][0], bh[1][2]);
            MMA16(sacc[3], ah0, ah1, ah2, ah3, bh[1][1], bh[1][3]);
        }
        float mx0 = -1e30f, mx1 = -1e30f;
        #pragma unroll
        for (int tt = 0; tt < 4; tt++) {
            mx0 = fmaxf(mx0, fmaxf(sacc[tt][0], sacc[tt][1]));
            mx1 = fmaxf(mx1, fmaxf(sacc[tt][2], sacc[tt][3]));
        }
        mx0 = fmaxf(mx0, __shfl_xor_sync(0xFFFFFFFFu, mx0, 1));
        mx0 = fmaxf(mx0, __shfl_xor_sync(0xFFFFFFFFu, mx0, 2));
        mx1 = fmaxf(mx1, __shfl_xor_sync(0xFFFFFFFFu, mx1, 1));
        mx1 = fmaxf(mx1, __shfl_xor_sync(0xFFFFFFFFu, mx1, 2));
        if (tig == 0) {
            smf[RM + row0 * 2 + ch] = mx0;
            smf[RM + row1 * 2 + ch] = mx1;
        }
        __syncthreads();

        // online softmax -> P fp16
        float mn0 = fmaxf(rm0, fmaxf(smf[RM + row0 * 2], smf[RM + row0 * 2 + 1]));
        float mn1 = fmaxf(rm1, fmaxf(smf[RM + row1 * 2], smf[RM + row1 * 2 + 1]));
        float f0 = fast_exp2(rm0 - mn0), f1 = fast_exp2(rm1 - mn1);
        rm0 = mn0; rm1 = mn1;
        if (tig == 0 && ch == 0) { smf[FF + row0] = f0; smf[FF + row1] = f1; }
        float ps0 = 0.f, ps1 = 0.f;
        #pragma unroll
        for (int tt = 0; tt < 4; tt++) {
            float p00 = fast_exp2(sacc[tt][0] - mn0);
            float p01 = fast_exp2(sacc[tt][1] - mn0);
            float p10 = fast_exp2(sacc[tt][2] - mn1);
            float p11 = fast_exp2(sacc[tt][3] - mn1);
            ps0 += p00 + p01; ps1 += p10 + p11;
            __half2 h0 = __floats2half2_rn(p00, p01);
            __half2 h1 = __floats2half2_rn(p10, p11);
            const int cc = ch * 32 + tt * 8 + 2 * tig;
            *(uint32_t*)(smh + SP + row0 * 72 + cc) = *(uint32_t*)&h0;
            *(uint32_t*)(smh + SP + row1 * 72 + cc) = *(uint32_t*)&h1;
        }
        lsum0 = lsum0 * f0 + ps0;
        lsum1 = lsum1 * f1 + ps1;
        CPWAITG(1);        // V(t) ready; K(t+1) may pend
        __syncthreads();   // P + V visible

        // rescale O (skipped when no row max changed), then O += P.V^T
        float fa0 = smf[FF + rq + gid], fa1 = smf[FF + rq + gid + 8];
        float fb0 = smf[FF + rq + 16 + gid], fb1 = smf[FF + rq + 16 + gid + 8];
        if (!__all_sync(0xFFFFFFFFu,
                        (fa0 == 1.f) & (fa1 == 1.f) & (fb0 == 1.f) & (fb1 == 1.f))) {
            #pragma unroll
            for (int nt = 0; nt < 8; nt++) {
                oacc[nt][0] *= fa0; oacc[nt][1] *= fa0;
                oacc[nt][2] *= fa1; oacc[nt][3] *= fa1;
                oacc[8 + nt][0] *= fb0; oacc[8 + nt][1] *= fb0;
                oacc[8 + nt][2] *= fb1; oacc[8 + nt][3] *= fb1;
            }
        }
        #pragma unroll
        for (int kk = 0; kk < 4; kk++) {
            uint32_t pa0, pa1, pa2, pa3, qa0, qa1, qa2, qa3;
            uint32_t ap = sb + 2u * (SP + (rq + lr) * 72 + kk * 16 + lc);
            LDSM4(pa0, pa1, pa2, pa3, ap);
            LDSM4(qa0, qa1, qa2, qa3, ap + 2u * (16 * 72));
            const uint32_t cb = (uint32_t)(kk * 2 + (lc >> 3));
            #pragma unroll
            for (int np = 0; np < 4; np++) {
                const int vrow = cq + np * 16 + lr;
                uint32_t va = sb + VBB + vrow * 128 + ((cb ^ (uint32_t)(vrow & 7)) << 4);
                uint32_t v0, v1, v2, v3;
                LDSM4(v0, v1, v2, v3, va);
                MMA16(oacc[2 * np],         pa0, pa1, pa2, pa3, v0, v2);
                MMA16(oacc[2 * np + 1],     pa0, pa1, pa2, pa3, v1, v3);
                MMA16(oacc[8 + 2 * np],     qa0, qa1, qa2, qa3, v0, v2);
                MMA16(oacc[8 + 2 * np + 1], qa0, qa1, qa2, qa3, v1, v3);
            }
        }
    }

    // final l reduction + epilogue
    lsum0 += __shfl_xor_sync(0xFFFFFFFFu, lsum0, 1);
    lsum0 += __shfl_xor_sync(0xFFFFFFFFu, lsum0, 2);
    lsum1 += __shfl_xor_sync(0xFFFFFFFFu, lsum1, 1);
    lsum1 += __shfl_xor_sync(0xFFFFFFFFu, lsum1, 2);
    __syncthreads();
    if (tig == 0) {
        smf[LR + row0 * 2 + ch] = lsum0;
        smf[LR + row1 * 2 + ch] = lsum1;
    }
    __syncthreads();

    const float gm = __ldg(gamma);
    const float* skb = skip + (size_t)b * CVCH * NTOK;
    float* ob = out + (size_t)b * CVCH * NTOK;
    #pragma unroll
    for (int mt = 0; mt < 2; mt++) {
        const int ra = rq + mt * 16 + gid, rb = ra + 8;
        const float fca = gm / (smf[LR + ra * 2] + smf[LR + ra * 2 + 1]);
        const float fcb = gm / (smf[LR + rb * 2] + smf[LR + rb * 2 + 1]);
        const int ia = i0 + ra, ib = i0 + rb;
        #pragma unroll
        for (int nt = 0; nt < 8; nt++) {
            const int c = cq + nt * 8 + 2 * tig;
            const size_t oA = (size_t)c * NTOK, oB = (size_t)(c + 1) * NTOK;
            const float* acc = oacc[mt * 8 + nt];
            ob[oA + ia] = acc[0] * fca + skb[oA + ia];
            ob[oB + ia] = acc[1] * fca + skb[oB + ia];
            ob[oA + ib] = acc[2] * fcb + skb[oA + ib];
            ob[oB + ib] = acc[3] * fcb + skb[oB + ib];
        }
    }
}

// ---------------------------------------------------------------------------
static __half* s_q = nullptr;
static __half* s_k = nullptr;
static __half* s_v = nullptr;

extern "C" void kernel_launch(void* const* d_in, const int* in_sizes, int n_in,
                              void* d_out, int out_size) {
    (void)in_sizes; (void)n_in; (void)out_size;
    static bool initialized = []() {
        void* p;
        cudaGetSymbolAddress(&p, g_q16); s_q = (__half*)p;
        cudaGetSymbolAddress(&p, g_k16); s_k = (__half*)p;
        cudaGetSymbolAddress(&p, g_v16); s_v = (__half*)p;
        cudaFuncSetAttribute(attn_kernel, cudaFuncAttributeMaxDynamicSharedMemorySize,
                             ATTN_SMEM);
        return true;
    }();
    (void)initialized;

    const float* gate  = (const float*)d_in[0];
    const float* skip  = (const float*)d_in[1];
    const float* Wq    = (const float*)d_in[2];
    const float* bq    = (const float*)d_in[3];
    const float* Wk    = (const float*)d_in[4];
    const float* bk    = (const float*)d_in[5];
    const float* Wv    = (const float*)d_in[6];
    const float* bv    = (const float*)d_in[7];
    const float* gamma = (const float*)d_in[8];
    float* out = (float*)d_out;

    const float LOG2E = 1.4426950408889634f;

    fused_conv<<<dim3(128, 1, NB), 256>>>(gate, skip, Wq, bq, Wk, bk, Wv, bv,
                                          s_q, s_k, s_v, LOG2E);
    attn_kernel<<<dim3(NTOK / TQ, NB), 256, ATTN_SMEM>>>(skip, gamma, out);
}